// round 11
// baseline (speedup 1.0000x reference)
#include <cuda_runtime.h>
#include <cuda_fp16.h>
#include <stdint.h>

#define SQ 2048
#define DH 64
#define NH_ 16
#define NB_ 4
#define KT 32
#define NTILES (SQ/KT)
#define OUT_ELEMS (NB_*NH_*SQ*DH)
#define RSTRIDE 144
#define QSCALE 0.18033688011112042f   // 0.125 * log2(e); exp(s) = exp2(S)

__device__ unsigned g_maskbits[(size_t)NB_ * SQ * (SQ / 32)];   // 2 MB
__device__ float    g_linv[(size_t)NB_ * NH_ * SQ];             // 512 KB
__device__ uint4    g_pstash[(size_t)1024 * NTILES * 512];      // 512 MB: e in A-frag layout

// pass A smem: Q hi + K hi double buffer (identical to R8 pass0)
#define P0_QH 0
#define P0_KH(bf) (18432 + (bf)*4608)
#define SMEM_A 27648
// pass B smem: V hi double buffer only
#define SVH(bf) ((bf)*4608)
#define SMEM_B 9216

// ---------------- PTX helpers ----------------
__device__ __forceinline__ void ldsm4(uint32_t* r, uint32_t a) {
    asm volatile("ldmatrix.sync.aligned.m8n8.x4.shared.b16 {%0,%1,%2,%3}, [%4];"
                 : "=r"(r[0]), "=r"(r[1]), "=r"(r[2]), "=r"(r[3]) : "r"(a));
}
__device__ __forceinline__ void ldsm4t(uint32_t* r, uint32_t a) {
    asm volatile("ldmatrix.sync.aligned.m8n8.x4.trans.shared.b16 {%0,%1,%2,%3}, [%4];"
                 : "=r"(r[0]), "=r"(r[1]), "=r"(r[2]), "=r"(r[3]) : "r"(a));
}
__device__ __forceinline__ void mma16816(float* c, const uint32_t* a, const uint32_t* b) {
    asm volatile("mma.sync.aligned.m16n8k16.row.col.f32.f16.f16.f32 "
                 "{%0,%1,%2,%3}, {%4,%5,%6,%7}, {%8,%9}, {%0,%1,%2,%3};"
                 : "+f"(c[0]), "+f"(c[1]), "+f"(c[2]), "+f"(c[3])
                 : "r"(a[0]), "r"(a[1]), "r"(a[2]), "r"(a[3]), "r"(b[0]), "r"(b[1]));
}
__device__ __forceinline__ uint32_t packh(float x, float y) {
    __half2 h = __halves2half2(__float2half_rn(x), __float2half_rn(y));
    return *reinterpret_cast<uint32_t*>(&h);
}
__device__ __forceinline__ float2 unpackh(uint32_t u, float s) {
    __half2 h = *reinterpret_cast<__half2*>(&u);
    return make_float2(__low2float(h) * s, __high2float(h) * s);
}
__device__ __forceinline__ void sts_f4h(char* sm, int off, int lin, float4 x) {
    uint32_t a = (uint32_t)(lin >> 4) * RSTRIDE + (uint32_t)(lin & 15) * 8;
    *reinterpret_cast<uint2*>(sm + off + a) = make_uint2(packh(x.x, x.y), packh(x.z, x.w));
}

// ---------------- mask bit-pack ----------------
__global__ void maskpack_kernel(const int* __restrict__ mask) {
    int gwarp = blockIdx.x * 8 + (threadIdx.x >> 5);
    int lane = threadIdx.x & 31;
    size_t base = (size_t)gwarp * 128;
    unsigned b0 = __ballot_sync(0xffffffffu, mask[base + lane] != 0);
    unsigned b1 = __ballot_sync(0xffffffffu, mask[base + 32 + lane] != 0);
    unsigned b2 = __ballot_sync(0xffffffffu, mask[base + 64 + lane] != 0);
    unsigned b3 = __ballot_sync(0xffffffffu, mask[base + 96 + lane] != 0);
    if (lane == 0)
        *reinterpret_cast<uint4*>(&g_maskbits[(size_t)gwarp * 4]) = make_uint4(b0, b1, b2, b3);
}

// ---------------- pass A: QK once; stash e = mask*exp2(S) as fp16 frags; lsum ----------------
__global__ __launch_bounds__(256, 2)
void sdpa_passA(const float* __restrict__ qg, const float* __restrict__ kg)
{
    extern __shared__ char sm[];
    const uint32_t sb = (uint32_t)__cvta_generic_to_shared(sm);
    const int tid = threadIdx.x, warp = tid >> 5, lane = tid & 31;
    const int g = lane >> 2, t4 = lane & 3;
    const int qt = blockIdx.x, h = blockIdx.y, b = blockIdx.z;
    const int q0 = qt * 128;
    const size_t bh = (size_t)(b * NH_ + h);
    const float* qb = qg + (bh * SQ + (size_t)q0) * DH;
    const float* kb = kg + bh * SQ * DH;
    const int r0 = warp * 16 + g, r1 = r0 + 8;

    // Q -> smem f16 hi (scale folded); re-ldsm per tile (R8 pattern: low live-reg pressure)
#pragma unroll
    for (int i = 0; i < 8; i++) {
        int lin = i * 256 + tid;
        float4 x = reinterpret_cast<const float4*>(qb)[lin];
        x.x *= QSCALE; x.y *= QSCALE; x.z *= QSCALE; x.w *= QSCALE;
        sts_f4h(sm, P0_QH, lin, x);
    }
    float4 pk0 = reinterpret_cast<const float4*>(kb)[tid];
    float4 pk1 = reinterpret_cast<const float4*>(kb)[256 + tid];
    sts_f4h(sm, P0_KH(0), tid, pk0);
    sts_f4h(sm, P0_KH(0), 256 + tid, pk1);

    float lsum0 = 0.0f, lsum1 = 0.0f;
    const uint32_t qHaddr = sb + P0_QH + (uint32_t)(warp * 16 + (lane & 15)) * RSTRIDE
                          + (uint32_t)(lane >> 4) * 16;
    const uint32_t kfoff = (uint32_t)(lane & 7) * RSTRIDE + (uint32_t)(lane >> 3) * 16;
    const unsigned* mw0 = &g_maskbits[((size_t)b * SQ + q0 + r0) * (SQ / 32)];
    const unsigned* mw1 = &g_maskbits[((size_t)b * SQ + q0 + r1) * (SQ / 32)];
    const size_t cta = ((size_t)(b * NH_ + h)) * 16 + qt;
    uint4* stash = &g_pstash[cta * NTILES * 512 + (size_t)tid * 2];

    for (int t = 0; t < NTILES; t++) {
        const int cur = t & 1;
        unsigned w0 = mw0[t], w1 = mw1[t];
        if (t + 1 < NTILES) {
            const float4* ks = reinterpret_cast<const float4*>(kb + (size_t)(t + 1) * KT * DH);
            pk0 = ks[tid]; pk1 = ks[256 + tid];
        }
        __syncthreads();

        float S[4][4];
#pragma unroll
        for (int ng = 0; ng < 4; ng++)
#pragma unroll
            for (int j = 0; j < 4; j++) S[ng][j] = 0.0f;

#pragma unroll
        for (int kp = 0; kp < 2; kp++) {
            uint32_t qh0[4], qh1[4];
            ldsm4(qh0, qHaddr + kp * 64);
            ldsm4(qh1, qHaddr + kp * 64 + 32);
#pragma unroll
            for (int ng = 0; ng < 4; ng++) {
                uint32_t kh[4];
                ldsm4(kh, sb + P0_KH(cur) + (uint32_t)(ng * 8) * RSTRIDE + kp * 64 + kfoff);
                mma16816(S[ng], qh0, kh + 0);
                mma16816(S[ng], qh1, kh + 2);
            }
        }

        // e = mask*exp2(S); lsum; stash fp16 frags (streaming, coalesced)
#pragma unroll
        for (int ng = 0; ng < 4; ng++) {
            int j = 8 * ng + 2 * t4;
            S[ng][0] = ((w0 >> j) & 1u)       ? exp2f(S[ng][0]) : 0.0f;
            S[ng][1] = ((w0 >> (j + 1)) & 1u) ? exp2f(S[ng][1]) : 0.0f;
            S[ng][2] = ((w1 >> j) & 1u)       ? exp2f(S[ng][2]) : 0.0f;
            S[ng][3] = ((w1 >> (j + 1)) & 1u) ? exp2f(S[ng][3]) : 0.0f;
            lsum0 += S[ng][0] + S[ng][1];
            lsum1 += S[ng][2] + S[ng][3];
        }
        uint4 s0 = make_uint4(packh(S[0][0], S[0][1]), packh(S[0][2], S[0][3]),
                              packh(S[1][0], S[1][1]), packh(S[1][2], S[1][3]));
        uint4 s1 = make_uint4(packh(S[2][0], S[2][1]), packh(S[2][2], S[2][3]),
                              packh(S[3][0], S[3][1]), packh(S[3][2], S[3][3]));
        __stcs(stash + (size_t)t * 512, s0);
        __stcs(stash + (size_t)t * 512 + 1, s1);

        if (t + 1 < NTILES) {
            const int nxt = cur ^ 1;
            sts_f4h(sm, P0_KH(nxt), tid, pk0);
            sts_f4h(sm, P0_KH(nxt), 256 + tid, pk1);
        }
    }

    lsum0 += __shfl_xor_sync(0xffffffffu, lsum0, 1);
    lsum0 += __shfl_xor_sync(0xffffffffu, lsum0, 2);
    lsum1 += __shfl_xor_sync(0xffffffffu, lsum1, 1);
    lsum1 += __shfl_xor_sync(0xffffffffu, lsum1, 2);
    if (t4 == 0) {
        g_linv[bh * SQ + q0 + r0] = 1.0f / lsum0;
        g_linv[bh * SQ + q0 + r1] = 1.0f / lsum1;
    }
}

// ---------------- pass B: read e frags; attn = e*invl; O += P_hi V_hi ----------------
__global__ __launch_bounds__(256, 2)
void sdpa_passB(const float* __restrict__ vg, float* __restrict__ outg)
{
    extern __shared__ char sm[];
    const uint32_t sb = (uint32_t)__cvta_generic_to_shared(sm);
    const int tid = threadIdx.x, warp = tid >> 5, lane = tid & 31;
    const int g = lane >> 2, t4 = lane & 3;
    const int qt = blockIdx.x, h = blockIdx.y, b = blockIdx.z;
    const int q0 = qt * 128;
    const size_t bh = (size_t)(b * NH_ + h);
    const float* vb = vg + bh * SQ * DH;
    const int r0 = warp * 16 + g, r1 = r0 + 8;

    const float invl0 = g_linv[bh * SQ + q0 + r0];
    const float invl1 = g_linv[bh * SQ + q0 + r1];

    float4 pv0 = reinterpret_cast<const float4*>(vb)[tid];
    float4 pv1 = reinterpret_cast<const float4*>(vb)[256 + tid];
    sts_f4h(sm, SVH(0), tid, pv0);
    sts_f4h(sm, SVH(0), 256 + tid, pv1);

    float O[8][4];
#pragma unroll
    for (int n = 0; n < 8; n++)
#pragma unroll
        for (int j = 0; j < 4; j++) O[n][j] = 0.0f;

    const uint32_t vfoff = (uint32_t)(8 * (lane >> 3) + (lane & 7)) * RSTRIDE;
    float* attnb = outg + (size_t)OUT_ELEMS + (bh * SQ + (size_t)q0) * SQ;
    float* at0 = attnb + (size_t)r0 * SQ;
    float* at1 = attnb + (size_t)r1 * SQ;
    const size_t cta = ((size_t)(b * NH_ + h)) * 16 + qt;
    const uint4* stash = &g_pstash[cta * NTILES * 512 + (size_t)tid * 2];

    for (int t = 0; t < NTILES; t++) {
        const int cur = t & 1;
        // issue stash reads early (independent of smem)
        uint4 s0 = __ldcs(stash + (size_t)t * 512);
        uint4 s1 = __ldcs(stash + (size_t)t * 512 + 1);
        if (t + 1 < NTILES) {
            const float4* vs = reinterpret_cast<const float4*>(vb + (size_t)(t + 1) * KT * DH);
            pv0 = vs[tid]; pv1 = vs[256 + tid];
        }
        __syncthreads();   // V buf[cur] ready

        // normalize (fp32), write attn, build PV A-frags
        float2 p00 = unpackh(s0.x, invl0), p01 = unpackh(s0.y, invl1);
        float2 p10 = unpackh(s0.z, invl0), p11 = unpackh(s0.w, invl1);
        float2 p20 = unpackh(s1.x, invl0), p21 = unpackh(s1.y, invl1);
        float2 p30 = unpackh(s1.z, invl0), p31 = unpackh(s1.w, invl1);

        int c0 = t * KT + 2 * t4;
        __stcs(reinterpret_cast<float2*>(&at0[c0]),      p00);
        __stcs(reinterpret_cast<float2*>(&at1[c0]),      p01);
        __stcs(reinterpret_cast<float2*>(&at0[c0 + 8]),  p10);
        __stcs(reinterpret_cast<float2*>(&at1[c0 + 8]),  p11);
        __stcs(reinterpret_cast<float2*>(&at0[c0 + 16]), p20);
        __stcs(reinterpret_cast<float2*>(&at1[c0 + 16]), p21);
        __stcs(reinterpret_cast<float2*>(&at0[c0 + 24]), p30);
        __stcs(reinterpret_cast<float2*>(&at1[c0 + 24]), p31);

        uint32_t ahi[2][4];
        ahi[0][0] = packh(p00.x, p00.y); ahi[0][1] = packh(p01.x, p01.y);
        ahi[0][2] = packh(p10.x, p10.y); ahi[0][3] = packh(p11.x, p11.y);
        ahi[1][0] = packh(p20.x, p20.y); ahi[1][1] = packh(p21.x, p21.y);
        ahi[1][2] = packh(p30.x, p30.y); ahi[1][3] = packh(p31.x, p31.y);

        // O += P_hi V_hi
#pragma unroll
        for (int n = 0; n < 8; n++) {
            uint32_t bh4[4];
            ldsm4t(bh4, sb + SVH(cur) + vfoff + 16 * n);
            mma16816(O[n], ahi[0], bh4 + 0);
            mma16816(O[n], ahi[1], bh4 + 2);
        }

        if (t + 1 < NTILES) {
            const int nxt = cur ^ 1;
            sts_f4h(sm, SVH(nxt), tid, pv0);
            sts_f4h(sm, SVH(nxt), 256 + tid, pv1);
        }
    }

    float* outb = outg + (bh * SQ + (size_t)q0) * DH;
#pragma unroll
    for (int n = 0; n < 8; n++) {
        int col = 8 * n + 2 * t4;
        *reinterpret_cast<float2*>(&outb[(size_t)r0 * DH + col]) = make_float2(O[n][0], O[n][1]);
        *reinterpret_cast<float2*>(&outb[(size_t)r1 * DH + col]) = make_float2(O[n][2], O[n][3]);
    }
}

extern "C" void kernel_launch(void* const* d_in, const int* in_sizes, int n_in,
                              void* d_out, int out_size) {
    const float* q   = (const float*)d_in[0];
    const float* k   = (const float*)d_in[1];
    const float* v   = (const float*)d_in[2];
    const int*   msk = (const int*)d_in[3];
    float* out = (float*)d_out;

    cudaFuncSetAttribute(sdpa_passA, cudaFuncAttributeMaxDynamicSharedMemorySize, SMEM_A);
    cudaFuncSetAttribute(sdpa_passB, cudaFuncAttributeMaxDynamicSharedMemorySize, SMEM_B);

    maskpack_kernel<<<(NB_ * SQ * SQ) / (128 * 8), 256>>>(msk);
    dim3 grid(SQ / 128, NH_, NB_);
    sdpa_passA<<<grid, 256, SMEM_A>>>(q, k);
    sdpa_passB<<<grid, 256, SMEM_B>>>(v, out);
}

// round 12
// speedup vs baseline: 1.1508x; 1.1508x over previous
#include <cuda_runtime.h>
#include <cuda_fp16.h>
#include <stdint.h>

#define SQ 2048
#define DH 64
#define NH_ 16
#define NB_ 4
#define KT 32
#define NTILES (SQ/KT)
#define OUT_ELEMS (NB_*NH_*SQ*DH)
#define RSTRIDE 144
#define QSCALE 0.18033688011112042f   // 0.125 * log2(e); exp(s) = exp2(S)

__device__ unsigned g_maskbits[(size_t)NB_ * SQ * (SQ / 32)];   // 2 MB
__device__ float    g_linv[(size_t)NB_ * NH_ * SQ];             // 512 KB

// pass0 smem: Q hi + K hi double buffer
#define P0_QH 0
#define P0_KH(bf) (18432 + (bf)*4608)
#define SMEM_0 27648
// pass1 smem: Q hi + K hi double + V hi double
#define SQH 0
#define SKH(bf) (18432 + (bf)*4608)
#define SVH(bf) (27648 + (bf)*4608)
#define SMEM_1 36864

// ---------------- PTX helpers ----------------
__device__ __forceinline__ void ldsm4(uint32_t* r, uint32_t a) {
    asm volatile("ldmatrix.sync.aligned.m8n8.x4.shared.b16 {%0,%1,%2,%3}, [%4];"
                 : "=r"(r[0]), "=r"(r[1]), "=r"(r[2]), "=r"(r[3]) : "r"(a));
}
__device__ __forceinline__ void ldsm4t(uint32_t* r, uint32_t a) {
    asm volatile("ldmatrix.sync.aligned.m8n8.x4.trans.shared.b16 {%0,%1,%2,%3}, [%4];"
                 : "=r"(r[0]), "=r"(r[1]), "=r"(r[2]), "=r"(r[3]) : "r"(a));
}
__device__ __forceinline__ void mma16816(float* c, const uint32_t* a, const uint32_t* b) {
    asm volatile("mma.sync.aligned.m16n8k16.row.col.f32.f16.f16.f32 "
                 "{%0,%1,%2,%3}, {%4,%5,%6,%7}, {%8,%9}, {%0,%1,%2,%3};"
                 : "+f"(c[0]), "+f"(c[1]), "+f"(c[2]), "+f"(c[3])
                 : "r"(a[0]), "r"(a[1]), "r"(a[2]), "r"(a[3]), "r"(b[0]), "r"(b[1]));
}
__device__ __forceinline__ uint32_t packh(float x, float y) {
    __half2 h = __halves2half2(__float2half_rn(x), __float2half_rn(y));
    return *reinterpret_cast<uint32_t*>(&h);
}
__device__ __forceinline__ void sts_f4h(char* sm, int off, int lin, float4 x) {
    uint32_t a = (uint32_t)(lin >> 4) * RSTRIDE + (uint32_t)(lin & 15) * 8;
    *reinterpret_cast<uint2*>(sm + off + a) = make_uint2(packh(x.x, x.y), packh(x.z, x.w));
}

// ---------------- mask bit-pack ----------------
__global__ void maskpack_kernel(const int* __restrict__ mask) {
    int gwarp = blockIdx.x * 8 + (threadIdx.x >> 5);
    int lane = threadIdx.x & 31;
    size_t base = (size_t)gwarp * 128;
    unsigned b0 = __ballot_sync(0xffffffffu, mask[base + lane] != 0);
    unsigned b1 = __ballot_sync(0xffffffffu, mask[base + 32 + lane] != 0);
    unsigned b2 = __ballot_sync(0xffffffffu, mask[base + 64 + lane] != 0);
    unsigned b3 = __ballot_sync(0xffffffffu, mask[base + 96 + lane] != 0);
    if (lane == 0)
        *reinterpret_cast<uint4*>(&g_maskbits[(size_t)gwarp * 4]) = make_uint4(b0, b1, b2, b3);
}

// ---------------- pass0: lsum via single-term fp16 QK (3 CTAs/SM) ----------------
__global__ __launch_bounds__(256, 3)
void sdpa_pass0(const float* __restrict__ qg, const float* __restrict__ kg)
{
    extern __shared__ char sm[];
    const uint32_t sb = (uint32_t)__cvta_generic_to_shared(sm);
    const int tid = threadIdx.x, warp = tid >> 5, lane = tid & 31;
    const int g = lane >> 2, t4 = lane & 3;
    const int qt = blockIdx.x, h = blockIdx.y, b = blockIdx.z;
    const int q0 = qt * 128;
    const size_t bh = (size_t)(b * NH_ + h);
    const float* qb = qg + (bh * SQ + (size_t)q0) * DH;
    const float* kb = kg + bh * SQ * DH;
    const int r0 = warp * 16 + g, r1 = r0 + 8;

#pragma unroll
    for (int i = 0; i < 8; i++) {
        int lin = i * 256 + tid;
        float4 x = reinterpret_cast<const float4*>(qb)[lin];
        x.x *= QSCALE; x.y *= QSCALE; x.z *= QSCALE; x.w *= QSCALE;
        sts_f4h(sm, P0_QH, lin, x);
    }
    float4 pk0 = reinterpret_cast<const float4*>(kb)[tid];
    float4 pk1 = reinterpret_cast<const float4*>(kb)[256 + tid];
    sts_f4h(sm, P0_KH(0), tid, pk0);
    sts_f4h(sm, P0_KH(0), 256 + tid, pk1);

    float lsum0 = 0.0f, lsum1 = 0.0f;
    const uint32_t qHaddr = sb + P0_QH + (uint32_t)(warp * 16 + (lane & 15)) * RSTRIDE
                          + (uint32_t)(lane >> 4) * 16;
    const uint32_t kfoff = (uint32_t)(lane & 7) * RSTRIDE + (uint32_t)(lane >> 3) * 16;
    const unsigned* mw0 = &g_maskbits[((size_t)b * SQ + q0 + r0) * (SQ / 32)];
    const unsigned* mw1 = &g_maskbits[((size_t)b * SQ + q0 + r1) * (SQ / 32)];

    for (int t = 0; t < NTILES; t++) {
        const int cur = t & 1;
        unsigned w0 = mw0[t], w1 = mw1[t];
        if (t + 1 < NTILES) {
            const float4* ks = reinterpret_cast<const float4*>(kb + (size_t)(t + 1) * KT * DH);
            pk0 = ks[tid]; pk1 = ks[256 + tid];
        }
        __syncthreads();

        float S[4][4];
#pragma unroll
        for (int ng = 0; ng < 4; ng++)
#pragma unroll
            for (int j = 0; j < 4; j++) S[ng][j] = 0.0f;

#pragma unroll
        for (int kp = 0; kp < 2; kp++) {
            uint32_t qh0[4], qh1[4];
            ldsm4(qh0, qHaddr + kp * 64);
            ldsm4(qh1, qHaddr + kp * 64 + 32);
#pragma unroll
            for (int ng = 0; ng < 4; ng++) {
                uint32_t kh[4];
                ldsm4(kh, sb + P0_KH(cur) + (uint32_t)(ng * 8) * RSTRIDE + kp * 64 + kfoff);
                mma16816(S[ng], qh0, kh + 0);
                mma16816(S[ng], qh1, kh + 2);
            }
        }

#pragma unroll
        for (int ng = 0; ng < 4; ng++) {
            int j = 8 * ng + 2 * t4;
            lsum0 += (((w0 >> j) & 1u)       ? exp2f(S[ng][0]) : 0.0f)
                   + (((w0 >> (j + 1)) & 1u) ? exp2f(S[ng][1]) : 0.0f);
            lsum1 += (((w1 >> j) & 1u)       ? exp2f(S[ng][2]) : 0.0f)
                   + (((w1 >> (j + 1)) & 1u) ? exp2f(S[ng][3]) : 0.0f);
        }

        if (t + 1 < NTILES) {
            const int nxt = cur ^ 1;
            sts_f4h(sm, P0_KH(nxt), tid, pk0);
            sts_f4h(sm, P0_KH(nxt), 256 + tid, pk1);
        }
    }

    lsum0 += __shfl_xor_sync(0xffffffffu, lsum0, 1);
    lsum0 += __shfl_xor_sync(0xffffffffu, lsum0, 2);
    lsum1 += __shfl_xor_sync(0xffffffffu, lsum1, 1);
    lsum1 += __shfl_xor_sync(0xffffffffu, lsum1, 2);
    if (t4 == 0) {
        g_linv[bh * SQ + q0 + r0] = 1.0f / lsum0;
        g_linv[bh * SQ + q0 + r1] = 1.0f / lsum1;
    }
}

// ---------------- pass1: QK 1-term; attn = p*invl; O += P_hi V_hi ----------------
__global__ __launch_bounds__(256, 2)
void sdpa_pass1(const float* __restrict__ qg, const float* __restrict__ kg,
                const float* __restrict__ vg, float* __restrict__ outg)
{
    extern __shared__ char sm[];
    const uint32_t sb = (uint32_t)__cvta_generic_to_shared(sm);
    const int tid = threadIdx.x, warp = tid >> 5, lane = tid & 31;
    const int g = lane >> 2, t4 = lane & 3;
    const int qt = blockIdx.x, h = blockIdx.y, b = blockIdx.z;
    const int q0 = qt * 128;
    const size_t bh = (size_t)(b * NH_ + h);
    const float* qb = qg + (bh * SQ + (size_t)q0) * DH;
    const float* kb = kg + bh * SQ * DH;
    const float* vb = vg + bh * SQ * DH;
    const int r0 = warp * 16 + g, r1 = r0 + 8;

    const float invl0 = g_linv[bh * SQ + q0 + r0];
    const float invl1 = g_linv[bh * SQ + q0 + r1];

#pragma unroll
    for (int i = 0; i < 8; i++) {
        int lin = i * 256 + tid;
        float4 x = reinterpret_cast<const float4*>(qb)[lin];
        x.x *= QSCALE; x.y *= QSCALE; x.z *= QSCALE; x.w *= QSCALE;
        sts_f4h(sm, SQH, lin, x);
    }
    float4 pk0 = reinterpret_cast<const float4*>(kb)[tid];
    float4 pk1 = reinterpret_cast<const float4*>(kb)[256 + tid];
    float4 pv0 = reinterpret_cast<const float4*>(vb)[tid];
    float4 pv1 = reinterpret_cast<const float4*>(vb)[256 + tid];
    sts_f4h(sm, SKH(0), tid, pk0);
    sts_f4h(sm, SKH(0), 256 + tid, pk1);
    sts_f4h(sm, SVH(0), tid, pv0);
    sts_f4h(sm, SVH(0), 256 + tid, pv1);

    float O[8][4];
#pragma unroll
    for (int n = 0; n < 8; n++)
#pragma unroll
        for (int j = 0; j < 4; j++) O[n][j] = 0.0f;

    const uint32_t qHaddr = sb + SQH + (uint32_t)(warp * 16 + (lane & 15)) * RSTRIDE
                          + (uint32_t)(lane >> 4) * 16;
    const uint32_t kfoff = (uint32_t)(lane & 7) * RSTRIDE + (uint32_t)(lane >> 3) * 16;
    const uint32_t vfoff = (uint32_t)(8 * (lane >> 3) + (lane & 7)) * RSTRIDE;
    const unsigned* mw0 = &g_maskbits[((size_t)b * SQ + q0 + r0) * (SQ / 32)];
    const unsigned* mw1 = &g_maskbits[((size_t)b * SQ + q0 + r1) * (SQ / 32)];
    float* attnb = outg + (size_t)OUT_ELEMS + (bh * SQ + (size_t)q0) * SQ;
    float* at0 = attnb + (size_t)r0 * SQ;
    float* at1 = attnb + (size_t)r1 * SQ;

    for (int t = 0; t < NTILES; t++) {
        const int cur = t & 1;
        unsigned w0 = mw0[t], w1 = mw1[t];
        if (t + 1 < NTILES) {
            const float4* ks = reinterpret_cast<const float4*>(kb + (size_t)(t + 1) * KT * DH);
            const float4* vs = reinterpret_cast<const float4*>(vb + (size_t)(t + 1) * KT * DH);
            pk0 = ks[tid]; pk1 = ks[256 + tid];
            pv0 = vs[tid]; pv1 = vs[256 + tid];
        }
        __syncthreads();

        // ---- S = Q_hi K_hi^T (identical arithmetic to pass0) ----
        float S[4][4];
#pragma unroll
        for (int ng = 0; ng < 4; ng++)
#pragma unroll
            for (int j = 0; j < 4; j++) S[ng][j] = 0.0f;

#pragma unroll
        for (int kp = 0; kp < 2; kp++) {
            uint32_t qh0[4], qh1[4];
            ldsm4(qh0, qHaddr + kp * 64);
            ldsm4(qh1, qHaddr + kp * 64 + 32);
#pragma unroll
            for (int ng = 0; ng < 4; ng++) {
                uint32_t kh[4];
                ldsm4(kh, sb + SKH(cur) + (uint32_t)(ng * 8) * RSTRIDE + kp * 64 + kfoff);
                mma16816(S[ng], qh0, kh + 0);
                mma16816(S[ng], qh1, kh + 2);
            }
        }

        // ---- p = mask*exp2(S)*invl; write attn; keep for PV ----
#pragma unroll
        for (int ng = 0; ng < 4; ng++) {
            int j = 8 * ng + 2 * t4;
            float e00 = ((w0 >> j) & 1u)       ? exp2f(S[ng][0]) * invl0 : 0.0f;
            float e01 = ((w0 >> (j + 1)) & 1u) ? exp2f(S[ng][1]) * invl0 : 0.0f;
            float e10 = ((w1 >> j) & 1u)       ? exp2f(S[ng][2]) * invl1 : 0.0f;
            float e11 = ((w1 >> (j + 1)) & 1u) ? exp2f(S[ng][3]) * invl1 : 0.0f;
            S[ng][0] = e00; S[ng][1] = e01; S[ng][2] = e10; S[ng][3] = e11;
            int col = t * KT + j;
            __stcs(reinterpret_cast<float2*>(&at0[col]), make_float2(e00, e01));
            __stcs(reinterpret_cast<float2*>(&at1[col]), make_float2(e10, e11));
        }

        // p -> A-frags (hi only)
        uint32_t ahi[2][4];
#pragma unroll
        for (int f = 0; f < 2; f++) {
            ahi[f][0] = packh(S[2*f][0],   S[2*f][1]);
            ahi[f][1] = packh(S[2*f][2],   S[2*f][3]);
            ahi[f][2] = packh(S[2*f+1][0], S[2*f+1][1]);
            ahi[f][3] = packh(S[2*f+1][2], S[2*f+1][3]);
        }

        // ---- O += P_hi V_hi ----
#pragma unroll
        for (int n = 0; n < 8; n++) {
            uint32_t bh4[4];
            ldsm4t(bh4, sb + SVH(cur) + vfoff + 16 * n);
            mma16816(O[n], ahi[0], bh4 + 0);
            mma16816(O[n], ahi[1], bh4 + 2);
        }

        if (t + 1 < NTILES) {
            const int nxt = cur ^ 1;
            sts_f4h(sm, SKH(nxt), tid, pk0);
            sts_f4h(sm, SKH(nxt), 256 + tid, pk1);
            sts_f4h(sm, SVH(nxt), tid, pv0);
            sts_f4h(sm, SVH(nxt), 256 + tid, pv1);
        }
    }

    float* outb = outg + (bh * SQ + (size_t)q0) * DH;
#pragma unroll
    for (int n = 0; n < 8; n++) {
        int col = 8 * n + 2 * t4;
        *reinterpret_cast<float2*>(&outb[(size_t)r0 * DH + col]) = make_float2(O[n][0], O[n][1]);
        *reinterpret_cast<float2*>(&outb[(size_t)r1 * DH + col]) = make_float2(O[n][2], O[n][3]);
    }
}

extern "C" void kernel_launch(void* const* d_in, const int* in_sizes, int n_in,
                              void* d_out, int out_size) {
    const float* q   = (const float*)d_in[0];
    const float* k   = (const float*)d_in[1];
    const float* v   = (const float*)d_in[2];
    const int*   msk = (const int*)d_in[3];
    float* out = (float*)d_out;

    cudaFuncSetAttribute(sdpa_pass0, cudaFuncAttributeMaxDynamicSharedMemorySize, SMEM_0);
    cudaFuncSetAttribute(sdpa_pass1, cudaFuncAttributeMaxDynamicSharedMemorySize, SMEM_1);

    maskpack_kernel<<<(NB_ * SQ * SQ) / (128 * 8), 256>>>(msk);
    dim3 grid(SQ / 128, NH_, NB_);
    sdpa_pass0<<<grid, 256, SMEM_0>>>(q, k);
    sdpa_pass1<<<grid, 256, SMEM_1>>>(q, k, v, out);
}

// round 13
// speedup vs baseline: 1.3653x; 1.1864x over previous
#include <cuda_runtime.h>
#include <cuda_fp16.h>
#include <stdint.h>

#define SQ 2048
#define DH 64
#define NH_ 16
#define NB_ 4
#define KT 32
#define NTILES (SQ/KT)
#define OUT_ELEMS (NB_*NH_*SQ*DH)
#define RSTRIDE 144
#define QSCALE 0.18033688011112042f   // 0.125 * log2(e); exp(s) = exp2(S)

__device__ unsigned g_maskbits[(size_t)NB_ * SQ * (SQ / 32)];   // 2 MB
__device__ float    g_linv[(size_t)NB_ * NH_ * SQ];             // 512 KB

// pass0 smem: Q hi + K hi double buffer
#define P0_QH 0
#define P0_KH(bf) (18432 + (bf)*4608)
#define SMEM_0 27648
// pass1 smem: Q hi + K hi double + V hi double
#define SQH 0
#define SKH(bf) (18432 + (bf)*4608)
#define SVH(bf) (27648 + (bf)*4608)
#define SMEM_1 36864

// ---------------- PTX helpers ----------------
__device__ __forceinline__ void ldsm4(uint32_t* r, uint32_t a) {
    asm volatile("ldmatrix.sync.aligned.m8n8.x4.shared.b16 {%0,%1,%2,%3}, [%4];"
                 : "=r"(r[0]), "=r"(r[1]), "=r"(r[2]), "=r"(r[3]) : "r"(a));
}
__device__ __forceinline__ void ldsm4t(uint32_t* r, uint32_t a) {
    asm volatile("ldmatrix.sync.aligned.m8n8.x4.trans.shared.b16 {%0,%1,%2,%3}, [%4];"
                 : "=r"(r[0]), "=r"(r[1]), "=r"(r[2]), "=r"(r[3]) : "r"(a));
}
__device__ __forceinline__ void mma16816(float* c, const uint32_t* a, const uint32_t* b) {
    asm volatile("mma.sync.aligned.m16n8k16.row.col.f32.f16.f16.f32 "
                 "{%0,%1,%2,%3}, {%4,%5,%6,%7}, {%8,%9}, {%0,%1,%2,%3};"
                 : "+f"(c[0]), "+f"(c[1]), "+f"(c[2]), "+f"(c[3])
                 : "r"(a[0]), "r"(a[1]), "r"(a[2]), "r"(a[3]), "r"(b[0]), "r"(b[1]));
}
__device__ __forceinline__ float ex2(float x) {
    float y;
    asm("ex2.approx.ftz.f32 %0, %1;" : "=f"(y) : "f"(x));
    return y;
}
__device__ __forceinline__ uint32_t packh(float x, float y) {
    __half2 h = __halves2half2(__float2half_rn(x), __float2half_rn(y));
    return *reinterpret_cast<uint32_t*>(&h);
}
__device__ __forceinline__ void sts_f4h(char* sm, int off, int lin, float4 x) {
    uint32_t a = (uint32_t)(lin >> 4) * RSTRIDE + (uint32_t)(lin & 15) * 8;
    *reinterpret_cast<uint2*>(sm + off + a) = make_uint2(packh(x.x, x.y), packh(x.z, x.w));
}

// ---------------- mask bit-pack ----------------
__global__ void maskpack_kernel(const int* __restrict__ mask) {
    int gwarp = blockIdx.x * 8 + (threadIdx.x >> 5);
    int lane = threadIdx.x & 31;
    size_t base = (size_t)gwarp * 128;
    unsigned b0 = __ballot_sync(0xffffffffu, mask[base + lane] != 0);
    unsigned b1 = __ballot_sync(0xffffffffu, mask[base + 32 + lane] != 0);
    unsigned b2 = __ballot_sync(0xffffffffu, mask[base + 64 + lane] != 0);
    unsigned b3 = __ballot_sync(0xffffffffu, mask[base + 96 + lane] != 0);
    if (lane == 0)
        *reinterpret_cast<uint4*>(&g_maskbits[(size_t)gwarp * 4]) = make_uint4(b0, b1, b2, b3);
}

// ---------------- pass0: lsum via single-term fp16 QK (3 CTAs/SM) ----------------
__global__ __launch_bounds__(256, 3)
void sdpa_pass0(const float* __restrict__ qg, const float* __restrict__ kg)
{
    extern __shared__ char sm[];
    const uint32_t sb = (uint32_t)__cvta_generic_to_shared(sm);
    const int tid = threadIdx.x, warp = tid >> 5, lane = tid & 31;
    const int g = lane >> 2, t4 = lane & 3;
    const int qt = blockIdx.x, h = blockIdx.y, b = blockIdx.z;
    const int q0 = qt * 128;
    const size_t bh = (size_t)(b * NH_ + h);
    const float* qb = qg + (bh * SQ + (size_t)q0) * DH;
    const float* kb = kg + bh * SQ * DH;
    const int r0 = warp * 16 + g, r1 = r0 + 8;

#pragma unroll
    for (int i = 0; i < 8; i++) {
        int lin = i * 256 + tid;
        float4 x = reinterpret_cast<const float4*>(qb)[lin];
        x.x *= QSCALE; x.y *= QSCALE; x.z *= QSCALE; x.w *= QSCALE;
        sts_f4h(sm, P0_QH, lin, x);
    }
    float4 pk0 = reinterpret_cast<const float4*>(kb)[tid];
    float4 pk1 = reinterpret_cast<const float4*>(kb)[256 + tid];
    sts_f4h(sm, P0_KH(0), tid, pk0);
    sts_f4h(sm, P0_KH(0), 256 + tid, pk1);

    float lsum0 = 0.0f, lsum1 = 0.0f;
    const uint32_t qHaddr = sb + P0_QH + (uint32_t)(warp * 16 + (lane & 15)) * RSTRIDE
                          + (uint32_t)(lane >> 4) * 16;
    const uint32_t kfoff = (uint32_t)(lane & 7) * RSTRIDE + (uint32_t)(lane >> 3) * 16;
    const unsigned* mw0 = &g_maskbits[((size_t)b * SQ + q0 + r0) * (SQ / 32)];
    const unsigned* mw1 = &g_maskbits[((size_t)b * SQ + q0 + r1) * (SQ / 32)];

    unsigned w0 = mw0[0], w1 = mw1[0];   // mask prefetched one tile ahead
    for (int t = 0; t < NTILES; t++) {
        const int cur = t & 1;
        unsigned w0c = w0, w1c = w1;
        if (t + 1 < NTILES) {
            const float4* ks = reinterpret_cast<const float4*>(kb + (size_t)(t + 1) * KT * DH);
            pk0 = ks[tid]; pk1 = ks[256 + tid];
            w0 = mw0[t + 1]; w1 = mw1[t + 1];
        }
        __syncthreads();

        float S[4][4];
#pragma unroll
        for (int ng = 0; ng < 4; ng++)
#pragma unroll
            for (int j = 0; j < 4; j++) S[ng][j] = 0.0f;

#pragma unroll
        for (int kp = 0; kp < 2; kp++) {
            uint32_t qh0[4], qh1[4];
            ldsm4(qh0, qHaddr + kp * 64);
            ldsm4(qh1, qHaddr + kp * 64 + 32);
#pragma unroll
            for (int ng = 0; ng < 4; ng++) {
                uint32_t kh[4];
                ldsm4(kh, sb + P0_KH(cur) + (uint32_t)(ng * 8) * RSTRIDE + kp * 64 + kfoff);
                mma16816(S[ng], qh0, kh + 0);
                mma16816(S[ng], qh1, kh + 2);
            }
        }

#pragma unroll
        for (int ng = 0; ng < 4; ng++) {
            int j = 8 * ng + 2 * t4;
            lsum0 += (((w0c >> j) & 1u)       ? ex2(S[ng][0]) : 0.0f)
                   + (((w0c >> (j + 1)) & 1u) ? ex2(S[ng][1]) : 0.0f);
            lsum1 += (((w1c >> j) & 1u)       ? ex2(S[ng][2]) : 0.0f)
                   + (((w1c >> (j + 1)) & 1u) ? ex2(S[ng][3]) : 0.0f);
        }

        if (t + 1 < NTILES) {
            const int nxt = cur ^ 1;
            sts_f4h(sm, P0_KH(nxt), tid, pk0);
            sts_f4h(sm, P0_KH(nxt), 256 + tid, pk1);
        }
    }

    lsum0 += __shfl_xor_sync(0xffffffffu, lsum0, 1);
    lsum0 += __shfl_xor_sync(0xffffffffu, lsum0, 2);
    lsum1 += __shfl_xor_sync(0xffffffffu, lsum1, 1);
    lsum1 += __shfl_xor_sync(0xffffffffu, lsum1, 2);
    if (t4 == 0) {
        g_linv[bh * SQ + q0 + r0] = 1.0f / lsum0;
        g_linv[bh * SQ + q0 + r1] = 1.0f / lsum1;
    }
}

// ---------------- pass1: QK 1-term; attn = p*invl; O += P_hi V_hi ----------------
__global__ __launch_bounds__(256, 2)
void sdpa_pass1(const float* __restrict__ qg, const float* __restrict__ kg,
                const float* __restrict__ vg, float* __restrict__ outg)
{
    extern __shared__ char sm[];
    const uint32_t sb = (uint32_t)__cvta_generic_to_shared(sm);
    const int tid = threadIdx.x, warp = tid >> 5, lane = tid & 31;
    const int g = lane >> 2, t4 = lane & 3;
    const int qt = blockIdx.x, h = blockIdx.y, b = blockIdx.z;
    const int q0 = qt * 128;
    const size_t bh = (size_t)(b * NH_ + h);
    const float* qb = qg + (bh * SQ + (size_t)q0) * DH;
    const float* kb = kg + bh * SQ * DH;
    const float* vb = vg + bh * SQ * DH;
    const int r0 = warp * 16 + g, r1 = r0 + 8;

    const float invl0 = g_linv[bh * SQ + q0 + r0];
    const float invl1 = g_linv[bh * SQ + q0 + r1];

#pragma unroll
    for (int i = 0; i < 8; i++) {
        int lin = i * 256 + tid;
        float4 x = reinterpret_cast<const float4*>(qb)[lin];
        x.x *= QSCALE; x.y *= QSCALE; x.z *= QSCALE; x.w *= QSCALE;
        sts_f4h(sm, SQH, lin, x);
    }
    float4 pk0 = reinterpret_cast<const float4*>(kb)[tid];
    float4 pk1 = reinterpret_cast<const float4*>(kb)[256 + tid];
    float4 pv0 = reinterpret_cast<const float4*>(vb)[tid];
    float4 pv1 = reinterpret_cast<const float4*>(vb)[256 + tid];
    sts_f4h(sm, SKH(0), tid, pk0);
    sts_f4h(sm, SKH(0), 256 + tid, pk1);
    sts_f4h(sm, SVH(0), tid, pv0);
    sts_f4h(sm, SVH(0), 256 + tid, pv1);

    float O[8][4];
#pragma unroll
    for (int n = 0; n < 8; n++)
#pragma unroll
        for (int j = 0; j < 4; j++) O[n][j] = 0.0f;

    const uint32_t qHaddr = sb + SQH + (uint32_t)(warp * 16 + (lane & 15)) * RSTRIDE
                          + (uint32_t)(lane >> 4) * 16;
    const uint32_t kfoff = (uint32_t)(lane & 7) * RSTRIDE + (uint32_t)(lane >> 3) * 16;
    const uint32_t vfoff = (uint32_t)(8 * (lane >> 3) + (lane & 7)) * RSTRIDE;
    const unsigned* mw0 = &g_maskbits[((size_t)b * SQ + q0 + r0) * (SQ / 32)];
    const unsigned* mw1 = &g_maskbits[((size_t)b * SQ + q0 + r1) * (SQ / 32)];
    float* attnb = outg + (size_t)OUT_ELEMS + (bh * SQ + (size_t)q0) * SQ;
    float* at0 = attnb + (size_t)r0 * SQ;
    float* at1 = attnb + (size_t)r1 * SQ;

    unsigned w0 = mw0[0], w1 = mw1[0];   // mask prefetched one tile ahead
    for (int t = 0; t < NTILES; t++) {
        const int cur = t & 1;
        unsigned w0c = w0, w1c = w1;
        if (t + 1 < NTILES) {
            const float4* ks = reinterpret_cast<const float4*>(kb + (size_t)(t + 1) * KT * DH);
            const float4* vs = reinterpret_cast<const float4*>(vb + (size_t)(t + 1) * KT * DH);
            pk0 = ks[tid]; pk1 = ks[256 + tid];
            pv0 = vs[tid]; pv1 = vs[256 + tid];
            w0 = mw0[t + 1]; w1 = mw1[t + 1];
        }
        __syncthreads();

        // ---- S = Q_hi K_hi^T (identical arithmetic to pass0) ----
        float S[4][4];
#pragma unroll
        for (int ng = 0; ng < 4; ng++)
#pragma unroll
            for (int j = 0; j < 4; j++) S[ng][j] = 0.0f;

#pragma unroll
        for (int kp = 0; kp < 2; kp++) {
            uint32_t qh0[4], qh1[4];
            ldsm4(qh0, qHaddr + kp * 64);
            ldsm4(qh1, qHaddr + kp * 64 + 32);
#pragma unroll
            for (int ng = 0; ng < 4; ng++) {
                uint32_t kh[4];
                ldsm4(kh, sb + SKH(cur) + (uint32_t)(ng * 8) * RSTRIDE + kp * 64 + kfoff);
                mma16816(S[ng], qh0, kh + 0);
                mma16816(S[ng], qh1, kh + 2);
            }
        }

        // ---- p = mask*exp2(S)*invl; write attn; keep for PV ----
#pragma unroll
        for (int ng = 0; ng < 4; ng++) {
            int j = 8 * ng + 2 * t4;
            float e00 = ((w0c >> j) & 1u)       ? ex2(S[ng][0]) * invl0 : 0.0f;
            float e01 = ((w0c >> (j + 1)) & 1u) ? ex2(S[ng][1]) * invl0 : 0.0f;
            float e10 = ((w1c >> j) & 1u)       ? ex2(S[ng][2]) * invl1 : 0.0f;
            float e11 = ((w1c >> (j + 1)) & 1u) ? ex2(S[ng][3]) * invl1 : 0.0f;
            S[ng][0] = e00; S[ng][1] = e01; S[ng][2] = e10; S[ng][3] = e11;
            int col = t * KT + j;
            __stcs(reinterpret_cast<float2*>(&at0[col]), make_float2(e00, e01));
            __stcs(reinterpret_cast<float2*>(&at1[col]), make_float2(e10, e11));
        }

        // p -> A-frags (hi only)
        uint32_t ahi[2][4];
#pragma unroll
        for (int f = 0; f < 2; f++) {
            ahi[f][0] = packh(S[2*f][0],   S[2*f][1]);
            ahi[f][1] = packh(S[2*f][2],   S[2*f][3]);
            ahi[f][2] = packh(S[2*f+1][0], S[2*f+1][1]);
            ahi[f][3] = packh(S[2*f+1][2], S[2*f+1][3]);
        }

        // ---- O += P_hi V_hi ----
#pragma unroll
        for (int n = 0; n < 8; n++) {
            uint32_t bh4[4];
            ldsm4t(bh4, sb + SVH(cur) + vfoff + 16 * n);
            mma16816(O[n], ahi[0], bh4 + 0);
            mma16816(O[n], ahi[1], bh4 + 2);
        }

        if (t + 1 < NTILES) {
            const int nxt = cur ^ 1;
            sts_f4h(sm, SKH(nxt), tid, pk0);
            sts_f4h(sm, SKH(nxt), 256 + tid, pk1);
            sts_f4h(sm, SVH(nxt), tid, pv0);
            sts_f4h(sm, SVH(nxt), 256 + tid, pv1);
        }
    }

    float* outb = outg + (bh * SQ + (size_t)q0) * DH;
#pragma unroll
    for (int n = 0; n < 8; n++) {
        int col = 8 * n + 2 * t4;
        *reinterpret_cast<float2*>(&outb[(size_t)r0 * DH + col]) = make_float2(O[n][0], O[n][1]);
        *reinterpret_cast<float2*>(&outb[(size_t)r1 * DH + col]) = make_float2(O[n][2], O[n][3]);
    }
}

extern "C" void kernel_launch(void* const* d_in, const int* in_sizes, int n_in,
                              void* d_out, int out_size) {
    const float* q   = (const float*)d_in[0];
    const float* k   = (const float*)d_in[1];
    const float* v   = (const float*)d_in[2];
    const int*   msk = (const int*)d_in[3];
    float* out = (float*)d_out;

    cudaFuncSetAttribute(sdpa_pass0, cudaFuncAttributeMaxDynamicSharedMemorySize, SMEM_0);
    cudaFuncSetAttribute(sdpa_pass1, cudaFuncAttributeMaxDynamicSharedMemorySize, SMEM_1);

    maskpack_kernel<<<(NB_ * SQ * SQ) / (128 * 8), 256>>>(msk);
    dim3 grid(SQ / 128, NH_, NB_);
    sdpa_pass0<<<grid, 256, SMEM_0>>>(q, k);
    sdpa_pass1<<<grid, 256, SMEM_1>>>(q, k, v, out);
}

// round 14
// speedup vs baseline: 1.3657x; 1.0003x over previous
#include <cuda_runtime.h>
#include <cuda_fp16.h>
#include <stdint.h>

#define SQ 2048
#define DH 64
#define NH_ 16
#define NB_ 4
#define KT 32
#define NTILES (SQ/KT)
#define OUT_ELEMS (NB_*NH_*SQ*DH)
#define RSTRIDE 144
#define QSCALE 0.18033688011112042f   // 0.125 * log2(e); exp(s) = exp2(S)

__device__ unsigned g_maskbits[(size_t)NB_ * SQ * (SQ / 32)];   // 2 MB
__device__ float    g_linv[(size_t)NB_ * NH_ * SQ];             // 512 KB

// pass0 smem: Q hi + K hi double buffer
#define P0_QH 0
#define P0_KH(bf) (18432 + (bf)*4608)
#define SMEM_0 27648
// pass1 smem: Q hi + K hi double + V hi double
#define SQH 0
#define SKH(bf) (18432 + (bf)*4608)
#define SVH(bf) (27648 + (bf)*4608)
#define SMEM_1 36864

// ---------------- PTX helpers ----------------
__device__ __forceinline__ void ldsm4(uint32_t* r, uint32_t a) {
    asm volatile("ldmatrix.sync.aligned.m8n8.x4.shared.b16 {%0,%1,%2,%3}, [%4];"
                 : "=r"(r[0]), "=r"(r[1]), "=r"(r[2]), "=r"(r[3]) : "r"(a));
}
__device__ __forceinline__ void ldsm4t(uint32_t* r, uint32_t a) {
    asm volatile("ldmatrix.sync.aligned.m8n8.x4.trans.shared.b16 {%0,%1,%2,%3}, [%4];"
                 : "=r"(r[0]), "=r"(r[1]), "=r"(r[2]), "=r"(r[3]) : "r"(a));
}
__device__ __forceinline__ void mma16816(float* c, const uint32_t* a, const uint32_t* b) {
    asm volatile("mma.sync.aligned.m16n8k16.row.col.f32.f16.f16.f32 "
                 "{%0,%1,%2,%3}, {%4,%5,%6,%7}, {%8,%9}, {%0,%1,%2,%3};"
                 : "+f"(c[0]), "+f"(c[1]), "+f"(c[2]), "+f"(c[3])
                 : "r"(a[0]), "r"(a[1]), "r"(a[2]), "r"(a[3]), "r"(b[0]), "r"(b[1]));
}
__device__ __forceinline__ float ex2(float x) {
    float y;
    asm("ex2.approx.ftz.f32 %0, %1;" : "=f"(y) : "f"(x));
    return y;
}
__device__ __forceinline__ uint32_t packh(float x, float y) {
    __half2 h = __halves2half2(__float2half_rn(x), __float2half_rn(y));
    return *reinterpret_cast<uint32_t*>(&h);
}
__device__ __forceinline__ void sts_f4h(char* sm, int off, int lin, float4 x) {
    uint32_t a = (uint32_t)(lin >> 4) * RSTRIDE + (uint32_t)(lin & 15) * 8;
    *reinterpret_cast<uint2*>(sm + off + a) = make_uint2(packh(x.x, x.y), packh(x.z, x.w));
}

// ---------------- mask bit-pack ----------------
__global__ void maskpack_kernel(const int* __restrict__ mask) {
    int gwarp = blockIdx.x * 8 + (threadIdx.x >> 5);
    int lane = threadIdx.x & 31;
    size_t base = (size_t)gwarp * 128;
    unsigned b0 = __ballot_sync(0xffffffffu, mask[base + lane] != 0);
    unsigned b1 = __ballot_sync(0xffffffffu, mask[base + 32 + lane] != 0);
    unsigned b2 = __ballot_sync(0xffffffffu, mask[base + 64 + lane] != 0);
    unsigned b3 = __ballot_sync(0xffffffffu, mask[base + 96 + lane] != 0);
    if (lane == 0)
        *reinterpret_cast<uint4*>(&g_maskbits[(size_t)gwarp * 4]) = make_uint4(b0, b1, b2, b3);
}

// ---------------- pass0: lsum via single-term fp16 QK (4 CTAs/SM) ----------------
__global__ __launch_bounds__(256, 4)
void sdpa_pass0(const float* __restrict__ qg, const float* __restrict__ kg)
{
    extern __shared__ char sm[];
    const uint32_t sb = (uint32_t)__cvta_generic_to_shared(sm);
    const int tid = threadIdx.x, warp = tid >> 5, lane = tid & 31;
    const int g = lane >> 2, t4 = lane & 3;
    const int qt = blockIdx.x, h = blockIdx.y, b = blockIdx.z;
    const int q0 = qt * 128;
    const size_t bh = (size_t)(b * NH_ + h);
    const float* qb = qg + (bh * SQ + (size_t)q0) * DH;
    const float* kb = kg + bh * SQ * DH;
    const int r0 = warp * 16 + g, r1 = r0 + 8;

#pragma unroll
    for (int i = 0; i < 8; i++) {
        int lin = i * 256 + tid;
        float4 x = reinterpret_cast<const float4*>(qb)[lin];
        x.x *= QSCALE; x.y *= QSCALE; x.z *= QSCALE; x.w *= QSCALE;
        sts_f4h(sm, P0_QH, lin, x);
    }
    float4 pk0 = reinterpret_cast<const float4*>(kb)[tid];
    float4 pk1 = reinterpret_cast<const float4*>(kb)[256 + tid];
    sts_f4h(sm, P0_KH(0), tid, pk0);
    sts_f4h(sm, P0_KH(0), 256 + tid, pk1);

    float lsum0 = 0.0f, lsum1 = 0.0f;
    const uint32_t qHaddr = sb + P0_QH + (uint32_t)(warp * 16 + (lane & 15)) * RSTRIDE
                          + (uint32_t)(lane >> 4) * 16;
    const uint32_t kfoff = (uint32_t)(lane & 7) * RSTRIDE + (uint32_t)(lane >> 3) * 16;
    const unsigned* mw0 = &g_maskbits[((size_t)b * SQ + q0 + r0) * (SQ / 32)];
    const unsigned* mw1 = &g_maskbits[((size_t)b * SQ + q0 + r1) * (SQ / 32)];

    unsigned w0 = mw0[0], w1 = mw1[0];   // mask prefetched one tile ahead
    for (int t = 0; t < NTILES; t++) {
        const int cur = t & 1;
        unsigned w0c = w0, w1c = w1;
        if (t + 1 < NTILES) {
            const float4* ks = reinterpret_cast<const float4*>(kb + (size_t)(t + 1) * KT * DH);
            pk0 = ks[tid]; pk1 = ks[256 + tid];
            w0 = mw0[t + 1]; w1 = mw1[t + 1];
        }
        __syncthreads();

        float S[4][4];
#pragma unroll
        for (int ng = 0; ng < 4; ng++)
#pragma unroll
            for (int j = 0; j < 4; j++) S[ng][j] = 0.0f;

#pragma unroll
        for (int kp = 0; kp < 2; kp++) {
            uint32_t qh0[4], qh1[4];
            ldsm4(qh0, qHaddr + kp * 64);
            ldsm4(qh1, qHaddr + kp * 64 + 32);
#pragma unroll
            for (int ng = 0; ng < 4; ng++) {
                uint32_t kh[4];
                ldsm4(kh, sb + P0_KH(cur) + (uint32_t)(ng * 8) * RSTRIDE + kp * 64 + kfoff);
                mma16816(S[ng], qh0, kh + 0);
                mma16816(S[ng], qh1, kh + 2);
            }
        }

#pragma unroll
        for (int ng = 0; ng < 4; ng++) {
            int j = 8 * ng + 2 * t4;
            lsum0 += (((w0c >> j) & 1u)       ? ex2(S[ng][0]) : 0.0f)
                   + (((w0c >> (j + 1)) & 1u) ? ex2(S[ng][1]) : 0.0f);
            lsum1 += (((w1c >> j) & 1u)       ? ex2(S[ng][2]) : 0.0f)
                   + (((w1c >> (j + 1)) & 1u) ? ex2(S[ng][3]) : 0.0f);
        }

        if (t + 1 < NTILES) {
            const int nxt = cur ^ 1;
            sts_f4h(sm, P0_KH(nxt), tid, pk0);
            sts_f4h(sm, P0_KH(nxt), 256 + tid, pk1);
        }
    }

    lsum0 += __shfl_xor_sync(0xffffffffu, lsum0, 1);
    lsum0 += __shfl_xor_sync(0xffffffffu, lsum0, 2);
    lsum1 += __shfl_xor_sync(0xffffffffu, lsum1, 1);
    lsum1 += __shfl_xor_sync(0xffffffffu, lsum1, 2);
    if (t4 == 0) {
        g_linv[bh * SQ + q0 + r0] = 1.0f / lsum0;
        g_linv[bh * SQ + q0 + r1] = 1.0f / lsum1;
    }
}

// ---------------- pass1: QK 1-term; O += P_hi V_hi; attn = p*invl (stores after MMA) ----------------
__global__ __launch_bounds__(256, 2)
void sdpa_pass1(const float* __restrict__ qg, const float* __restrict__ kg,
                const float* __restrict__ vg, float* __restrict__ outg)
{
    extern __shared__ char sm[];
    const uint32_t sb = (uint32_t)__cvta_generic_to_shared(sm);
    const int tid = threadIdx.x, warp = tid >> 5, lane = tid & 31;
    const int g = lane >> 2, t4 = lane & 3;
    const int qt = blockIdx.x, h = blockIdx.y, b = blockIdx.z;
    const int q0 = qt * 128;
    const size_t bh = (size_t)(b * NH_ + h);
    const float* qb = qg + (bh * SQ + (size_t)q0) * DH;
    const float* kb = kg + bh * SQ * DH;
    const float* vb = vg + bh * SQ * DH;
    const int r0 = warp * 16 + g, r1 = r0 + 8;

    const float invl0 = g_linv[bh * SQ + q0 + r0];
    const float invl1 = g_linv[bh * SQ + q0 + r1];

#pragma unroll
    for (int i = 0; i < 8; i++) {
        int lin = i * 256 + tid;
        float4 x = reinterpret_cast<const float4*>(qb)[lin];
        x.x *= QSCALE; x.y *= QSCALE; x.z *= QSCALE; x.w *= QSCALE;
        sts_f4h(sm, SQH, lin, x);
    }
    float4 pk0 = reinterpret_cast<const float4*>(kb)[tid];
    float4 pk1 = reinterpret_cast<const float4*>(kb)[256 + tid];
    float4 pv0 = reinterpret_cast<const float4*>(vb)[tid];
    float4 pv1 = reinterpret_cast<const float4*>(vb)[256 + tid];
    sts_f4h(sm, SKH(0), tid, pk0);
    sts_f4h(sm, SKH(0), 256 + tid, pk1);
    sts_f4h(sm, SVH(0), tid, pv0);
    sts_f4h(sm, SVH(0), 256 + tid, pv1);

    float O[8][4];
#pragma unroll
    for (int n = 0; n < 8; n++)
#pragma unroll
        for (int j = 0; j < 4; j++) O[n][j] = 0.0f;

    const uint32_t qHaddr = sb + SQH + (uint32_t)(warp * 16 + (lane & 15)) * RSTRIDE
                          + (uint32_t)(lane >> 4) * 16;
    const uint32_t kfoff = (uint32_t)(lane & 7) * RSTRIDE + (uint32_t)(lane >> 3) * 16;
    const uint32_t vfoff = (uint32_t)(8 * (lane >> 3) + (lane & 7)) * RSTRIDE;
    const unsigned* mw0 = &g_maskbits[((size_t)b * SQ + q0 + r0) * (SQ / 32)];
    const unsigned* mw1 = &g_maskbits[((size_t)b * SQ + q0 + r1) * (SQ / 32)];
    float* attnb = outg + (size_t)OUT_ELEMS + (bh * SQ + (size_t)q0) * SQ;
    float* at0 = attnb + (size_t)r0 * SQ;
    float* at1 = attnb + (size_t)r1 * SQ;

    unsigned w0 = mw0[0], w1 = mw1[0];   // mask prefetched one tile ahead
    for (int t = 0; t < NTILES; t++) {
        const int cur = t & 1;
        unsigned w0c = w0, w1c = w1;
        if (t + 1 < NTILES) {
            const float4* ks = reinterpret_cast<const float4*>(kb + (size_t)(t + 1) * KT * DH);
            const float4* vs = reinterpret_cast<const float4*>(vb + (size_t)(t + 1) * KT * DH);
            pk0 = ks[tid]; pk1 = ks[256 + tid];
            pv0 = vs[tid]; pv1 = vs[256 + tid];
            w0 = mw0[t + 1]; w1 = mw1[t + 1];
        }
        __syncthreads();

        // ---- S = Q_hi K_hi^T (identical arithmetic to pass0) ----
        float S[4][4];
#pragma unroll
        for (int ng = 0; ng < 4; ng++)
#pragma unroll
            for (int j = 0; j < 4; j++) S[ng][j] = 0.0f;

#pragma unroll
        for (int kp = 0; kp < 2; kp++) {
            uint32_t qh0[4], qh1[4];
            ldsm4(qh0, qHaddr + kp * 64);
            ldsm4(qh1, qHaddr + kp * 64 + 32);
#pragma unroll
            for (int ng = 0; ng < 4; ng++) {
                uint32_t kh[4];
                ldsm4(kh, sb + SKH(cur) + (uint32_t)(ng * 8) * RSTRIDE + kp * 64 + kfoff);
                mma16816(S[ng], qh0, kh + 0);
                mma16816(S[ng], qh1, kh + 2);
            }
        }

        // ---- p = mask*exp2(S)*invl ----
#pragma unroll
        for (int ng = 0; ng < 4; ng++) {
            int j = 8 * ng + 2 * t4;
            S[ng][0] = ((w0c >> j) & 1u)       ? ex2(S[ng][0]) * invl0 : 0.0f;
            S[ng][1] = ((w0c >> (j + 1)) & 1u) ? ex2(S[ng][1]) * invl0 : 0.0f;
            S[ng][2] = ((w1c >> j) & 1u)       ? ex2(S[ng][2]) * invl1 : 0.0f;
            S[ng][3] = ((w1c >> (j + 1)) & 1u) ? ex2(S[ng][3]) * invl1 : 0.0f;
        }

        // ---- pack + PV MMA first (tensor pipe starts ASAP) ----
        uint32_t ahi[2][4];
#pragma unroll
        for (int f = 0; f < 2; f++) {
            ahi[f][0] = packh(S[2*f][0],   S[2*f][1]);
            ahi[f][1] = packh(S[2*f][2],   S[2*f][3]);
            ahi[f][2] = packh(S[2*f+1][0], S[2*f+1][1]);
            ahi[f][3] = packh(S[2*f+1][2], S[2*f+1][3]);
        }
#pragma unroll
        for (int n = 0; n < 8; n++) {
            uint32_t bh4[4];
            ldsm4t(bh4, sb + SVH(cur) + vfoff + 16 * n);
            mma16816(O[n], ahi[0], bh4 + 0);
            mma16816(O[n], ahi[1], bh4 + 2);
        }

        // ---- attn writeback drains in the shadow of next-tile staging ----
#pragma unroll
        for (int ng = 0; ng < 4; ng++) {
            int col = t * KT + 8 * ng + 2 * t4;
            __stcs(reinterpret_cast<float2*>(&at0[col]), make_float2(S[ng][0], S[ng][1]));
            __stcs(reinterpret_cast<float2*>(&at1[col]), make_float2(S[ng][2], S[ng][3]));
        }

        if (t + 1 < NTILES) {
            const int nxt = cur ^ 1;
            sts_f4h(sm, SKH(nxt), tid, pk0);
            sts_f4h(sm, SKH(nxt), 256 + tid, pk1);
            sts_f4h(sm, SVH(nxt), tid, pv0);
            sts_f4h(sm, SVH(nxt), 256 + tid, pv1);
        }
    }

    float* outb = outg + (bh * SQ + (size_t)q0) * DH;
#pragma unroll
    for (int n = 0; n < 8; n++) {
        int col = 8 * n + 2 * t4;
        *reinterpret_cast<float2*>(&outb[(size_t)r0 * DH + col]) = make_float2(O[n][0], O[n][1]);
        *reinterpret_cast<float2*>(&outb[(size_t)r1 * DH + col]) = make_float2(O[n][2], O[n][3]);
    }
}

extern "C" void kernel_launch(void* const* d_in, const int* in_sizes, int n_in,
                              void* d_out, int out_size) {
    const float* q   = (const float*)d_in[0];
    const float* k   = (const float*)d_in[1];
    const float* v   = (const float*)d_in[2];
    const int*   msk = (const int*)d_in[3];
    float* out = (float*)d_out;

    cudaFuncSetAttribute(sdpa_pass0, cudaFuncAttributeMaxDynamicSharedMemorySize, SMEM_0);
    cudaFuncSetAttribute(sdpa_pass1, cudaFuncAttributeMaxDynamicSharedMemorySize, SMEM_1);

    maskpack_kernel<<<(NB_ * SQ * SQ) / (128 * 8), 256>>>(msk);
    dim3 grid(SQ / 128, NH_, NB_);
    sdpa_pass0<<<grid, 256, SMEM_0>>>(q, k);
    sdpa_pass1<<<grid, 256, SMEM_1>>>(q, k, v, out);
}

// round 15
// speedup vs baseline: 1.3680x; 1.0017x over previous
#include <cuda_runtime.h>
#include <cuda_fp16.h>
#include <stdint.h>

#define SQ 2048
#define DH 64
#define NH_ 16
#define NB_ 4
#define KT 32
#define NTILES (SQ/KT)
#define OUT_ELEMS (NB_*NH_*SQ*DH)
#define RSTRIDE 144
#define QSCALE 0.18033688011112042f   // 0.125 * log2(e); exp(s) = exp2(S)
#define MASKED_S -1e30f               // -> -inf in fp16 -> ex2 -> +0

__device__ unsigned g_maskbits[(size_t)NB_ * SQ * (SQ / 32)];   // 2 MB
__device__ float    g_linv[(size_t)NB_ * NH_ * SQ];             // 512 KB

// pass0 smem: Q hi + K hi double buffer
#define P0_QH 0
#define P0_KH(bf) (18432 + (bf)*4608)
#define SMEM_0 27648
// pass1 smem: Q hi + K hi double + V hi double
#define SQH 0
#define SKH(bf) (18432 + (bf)*4608)
#define SVH(bf) (27648 + (bf)*4608)
#define SMEM_1 36864

// ---------------- PTX helpers ----------------
__device__ __forceinline__ void ldsm4(uint32_t* r, uint32_t a) {
    asm volatile("ldmatrix.sync.aligned.m8n8.x4.shared.b16 {%0,%1,%2,%3}, [%4];"
                 : "=r"(r[0]), "=r"(r[1]), "=r"(r[2]), "=r"(r[3]) : "r"(a));
}
__device__ __forceinline__ void ldsm4t(uint32_t* r, uint32_t a) {
    asm volatile("ldmatrix.sync.aligned.m8n8.x4.trans.shared.b16 {%0,%1,%2,%3}, [%4];"
                 : "=r"(r[0]), "=r"(r[1]), "=r"(r[2]), "=r"(r[3]) : "r"(a));
}
__device__ __forceinline__ void mma16816(float* c, const uint32_t* a, const uint32_t* b) {
    asm volatile("mma.sync.aligned.m16n8k16.row.col.f32.f16.f16.f32 "
                 "{%0,%1,%2,%3}, {%4,%5,%6,%7}, {%8,%9}, {%0,%1,%2,%3};"
                 : "+f"(c[0]), "+f"(c[1]), "+f"(c[2]), "+f"(c[3])
                 : "r"(a[0]), "r"(a[1]), "r"(a[2]), "r"(a[3]), "r"(b[0]), "r"(b[1]));
}
// pack two f32 -> f16x2 (x in LOW half, y in HIGH half)
__device__ __forceinline__ uint32_t packh(float x, float y) {
    uint32_t r;
    asm("cvt.rn.f16x2.f32 %0, %1, %2;" : "=r"(r) : "f"(y), "f"(x));
    return r;
}
// exp2 on both halves of a f16x2 word
__device__ __forceinline__ uint32_t ex2h2(uint32_t x) {
    uint32_t y;
    asm("ex2.approx.f16x2 %0, %1;" : "=r"(y) : "r"(x));
    return y;
}
__device__ __forceinline__ uint32_t hmul2u(uint32_t a, uint32_t b) {
    uint32_t d;
    asm("mul.rn.f16x2 %0, %1, %2;" : "=r"(d) : "r"(a), "r"(b));
    return d;
}
__device__ __forceinline__ uint32_t hadd2u(uint32_t a, uint32_t b) {
    uint32_t d;
    asm("add.rn.f16x2 %0, %1, %2;" : "=r"(d) : "r"(a), "r"(b));
    return d;
}
__device__ __forceinline__ float2 h2_to_f2(uint32_t u) {
    __half2 h = *reinterpret_cast<__half2*>(&u);
    return make_float2(__low2float(h), __high2float(h));
}
__device__ __forceinline__ void sts_f4h(char* sm, int off, int lin, float4 x) {
    uint32_t a = (uint32_t)(lin >> 4) * RSTRIDE + (uint32_t)(lin & 15) * 8;
    *reinterpret_cast<uint2*>(sm + off + a) = make_uint2(packh(x.x, x.y), packh(x.z, x.w));
}

// ---------------- mask bit-pack ----------------
__global__ void maskpack_kernel(const int* __restrict__ mask) {
    int gwarp = blockIdx.x * 8 + (threadIdx.x >> 5);
    int lane = threadIdx.x & 31;
    size_t base = (size_t)gwarp * 128;
    unsigned b0 = __ballot_sync(0xffffffffu, mask[base + lane] != 0);
    unsigned b1 = __ballot_sync(0xffffffffu, mask[base + 32 + lane] != 0);
    unsigned b2 = __ballot_sync(0xffffffffu, mask[base + 64 + lane] != 0);
    unsigned b3 = __ballot_sync(0xffffffffu, mask[base + 96 + lane] != 0);
    if (lane == 0)
        *reinterpret_cast<uint4*>(&g_maskbits[(size_t)gwarp * 4]) = make_uint4(b0, b1, b2, b3);
}

// ---------------- pass0: lsum via single-term fp16 QK + f16x2 exp ----------------
__global__ __launch_bounds__(256, 4)
void sdpa_pass0(const float* __restrict__ qg, const float* __restrict__ kg)
{
    extern __shared__ char sm[];
    const uint32_t sb = (uint32_t)__cvta_generic_to_shared(sm);
    const int tid = threadIdx.x, warp = tid >> 5, lane = tid & 31;
    const int g = lane >> 2, t4 = lane & 3;
    const int qt = blockIdx.x, h = blockIdx.y, b = blockIdx.z;
    const int q0 = qt * 128;
    const size_t bh = (size_t)(b * NH_ + h);
    const float* qb = qg + (bh * SQ + (size_t)q0) * DH;
    const float* kb = kg + bh * SQ * DH;
    const int r0 = warp * 16 + g, r1 = r0 + 8;

#pragma unroll
    for (int i = 0; i < 8; i++) {
        int lin = i * 256 + tid;
        float4 x = reinterpret_cast<const float4*>(qb)[lin];
        x.x *= QSCALE; x.y *= QSCALE; x.z *= QSCALE; x.w *= QSCALE;
        sts_f4h(sm, P0_QH, lin, x);
    }
    float4 pk0 = reinterpret_cast<const float4*>(kb)[tid];
    float4 pk1 = reinterpret_cast<const float4*>(kb)[256 + tid];
    sts_f4h(sm, P0_KH(0), tid, pk0);
    sts_f4h(sm, P0_KH(0), 256 + tid, pk1);

    float lsum0 = 0.0f, lsum1 = 0.0f;
    const uint32_t qHaddr = sb + P0_QH + (uint32_t)(warp * 16 + (lane & 15)) * RSTRIDE
                          + (uint32_t)(lane >> 4) * 16;
    const uint32_t kfoff = (uint32_t)(lane & 7) * RSTRIDE + (uint32_t)(lane >> 3) * 16;
    const unsigned* mw0 = &g_maskbits[((size_t)b * SQ + q0 + r0) * (SQ / 32)];
    const unsigned* mw1 = &g_maskbits[((size_t)b * SQ + q0 + r1) * (SQ / 32)];

    unsigned w0 = mw0[0], w1 = mw1[0];
    for (int t = 0; t < NTILES; t++) {
        const int cur = t & 1;
        unsigned w0c = w0, w1c = w1;
        if (t + 1 < NTILES) {
            const float4* ks = reinterpret_cast<const float4*>(kb + (size_t)(t + 1) * KT * DH);
            pk0 = ks[tid]; pk1 = ks[256 + tid];
            w0 = mw0[t + 1]; w1 = mw1[t + 1];
        }
        __syncthreads();

        float S[4][4];
#pragma unroll
        for (int ng = 0; ng < 4; ng++)
#pragma unroll
            for (int j = 0; j < 4; j++) S[ng][j] = 0.0f;

#pragma unroll
        for (int kp = 0; kp < 2; kp++) {
            uint32_t qh0[4], qh1[4];
            ldsm4(qh0, qHaddr + kp * 64);
            ldsm4(qh1, qHaddr + kp * 64 + 32);
#pragma unroll
            for (int ng = 0; ng < 4; ng++) {
                uint32_t kh[4];
                ldsm4(kh, sb + P0_KH(cur) + (uint32_t)(ng * 8) * RSTRIDE + kp * 64 + kfoff);
                mma16816(S[ng], qh0, kh + 0);
                mma16816(S[ng], qh1, kh + 2);
            }
        }

        // mask -> -inf, f16x2 exp, hadd2 tree per row
        uint32_t e0[4], e1[4];
#pragma unroll
        for (int ng = 0; ng < 4; ng++) {
            int j = 8 * ng + 2 * t4;
            float s00 = ((w0c >> j) & 1u)       ? S[ng][0] : MASKED_S;
            float s01 = ((w0c >> (j + 1)) & 1u) ? S[ng][1] : MASKED_S;
            float s10 = ((w1c >> j) & 1u)       ? S[ng][2] : MASKED_S;
            float s11 = ((w1c >> (j + 1)) & 1u) ? S[ng][3] : MASKED_S;
            e0[ng] = ex2h2(packh(s00, s01));
            e1[ng] = ex2h2(packh(s10, s11));
        }
        uint32_t a0 = hadd2u(hadd2u(e0[0], e0[1]), hadd2u(e0[2], e0[3]));
        uint32_t a1 = hadd2u(hadd2u(e1[0], e1[1]), hadd2u(e1[2], e1[3]));
        float2 f0 = h2_to_f2(a0), f1 = h2_to_f2(a1);
        lsum0 += f0.x + f0.y;
        lsum1 += f1.x + f1.y;

        if (t + 1 < NTILES) {
            const int nxt = cur ^ 1;
            sts_f4h(sm, P0_KH(nxt), tid, pk0);
            sts_f4h(sm, P0_KH(nxt), 256 + tid, pk1);
        }
    }

    lsum0 += __shfl_xor_sync(0xffffffffu, lsum0, 1);
    lsum0 += __shfl_xor_sync(0xffffffffu, lsum0, 2);
    lsum1 += __shfl_xor_sync(0xffffffffu, lsum1, 1);
    lsum1 += __shfl_xor_sync(0xffffffffu, lsum1, 2);
    if (t4 == 0) {
        g_linv[bh * SQ + q0 + r0] = 1.0f / lsum0;
        g_linv[bh * SQ + q0 + r1] = 1.0f / lsum1;
    }
}

// ---------------- pass1: QK 1-term; f16x2 exp -> frags; O += P V; attn stores ----------------
__global__ __launch_bounds__(256, 2)
void sdpa_pass1(const float* __restrict__ qg, const float* __restrict__ kg,
                const float* __restrict__ vg, float* __restrict__ outg)
{
    extern __shared__ char sm[];
    const uint32_t sb = (uint32_t)__cvta_generic_to_shared(sm);
    const int tid = threadIdx.x, warp = tid >> 5, lane = tid & 31;
    const int g = lane >> 2, t4 = lane & 3;
    const int qt = blockIdx.x, h = blockIdx.y, b = blockIdx.z;
    const int q0 = qt * 128;
    const size_t bh = (size_t)(b * NH_ + h);
    const float* qb = qg + (bh * SQ + (size_t)q0) * DH;
    const float* kb = kg + bh * SQ * DH;
    const float* vb = vg + bh * SQ * DH;
    const int r0 = warp * 16 + g, r1 = r0 + 8;

    const float invl0 = g_linv[bh * SQ + q0 + r0];
    const float invl1 = g_linv[bh * SQ + q0 + r1];
    const uint32_t invl0h2 = packh(invl0, invl0);
    const uint32_t invl1h2 = packh(invl1, invl1);

#pragma unroll
    for (int i = 0; i < 8; i++) {
        int lin = i * 256 + tid;
        float4 x = reinterpret_cast<const float4*>(qb)[lin];
        x.x *= QSCALE; x.y *= QSCALE; x.z *= QSCALE; x.w *= QSCALE;
        sts_f4h(sm, SQH, lin, x);
    }
    float4 pk0 = reinterpret_cast<const float4*>(kb)[tid];
    float4 pk1 = reinterpret_cast<const float4*>(kb)[256 + tid];
    float4 pv0 = reinterpret_cast<const float4*>(vb)[tid];
    float4 pv1 = reinterpret_cast<const float4*>(vb)[256 + tid];
    sts_f4h(sm, SKH(0), tid, pk0);
    sts_f4h(sm, SKH(0), 256 + tid, pk1);
    sts_f4h(sm, SVH(0), tid, pv0);
    sts_f4h(sm, SVH(0), 256 + tid, pv1);

    float O[8][4];
#pragma unroll
    for (int n = 0; n < 8; n++)
#pragma unroll
        for (int j = 0; j < 4; j++) O[n][j] = 0.0f;

    const uint32_t qHaddr = sb + SQH + (uint32_t)(warp * 16 + (lane & 15)) * RSTRIDE
                          + (uint32_t)(lane >> 4) * 16;
    const uint32_t kfoff = (uint32_t)(lane & 7) * RSTRIDE + (uint32_t)(lane >> 3) * 16;
    const uint32_t vfoff = (uint32_t)(8 * (lane >> 3) + (lane & 7)) * RSTRIDE;
    const unsigned* mw0 = &g_maskbits[((size_t)b * SQ + q0 + r0) * (SQ / 32)];
    const unsigned* mw1 = &g_maskbits[((size_t)b * SQ + q0 + r1) * (SQ / 32)];
    float* attnb = outg + (size_t)OUT_ELEMS + (bh * SQ + (size_t)q0) * SQ;
    float* at0 = attnb + (size_t)r0 * SQ;
    float* at1 = attnb + (size_t)r1 * SQ;

    unsigned w0 = mw0[0], w1 = mw1[0];
    for (int t = 0; t < NTILES; t++) {
        const int cur = t & 1;
        unsigned w0c = w0, w1c = w1;
        if (t + 1 < NTILES) {
            const float4* ks = reinterpret_cast<const float4*>(kb + (size_t)(t + 1) * KT * DH);
            const float4* vs = reinterpret_cast<const float4*>(vb + (size_t)(t + 1) * KT * DH);
            pk0 = ks[tid]; pk1 = ks[256 + tid];
            pv0 = vs[tid]; pv1 = vs[256 + tid];
            w0 = mw0[t + 1]; w1 = mw1[t + 1];
        }
        __syncthreads();

        // ---- S = Q_hi K_hi^T ----
        float S[4][4];
#pragma unroll
        for (int ng = 0; ng < 4; ng++)
#pragma unroll
            for (int j = 0; j < 4; j++) S[ng][j] = 0.0f;

#pragma unroll
        for (int kp = 0; kp < 2; kp++) {
            uint32_t qh0[4], qh1[4];
            ldsm4(qh0, qHaddr + kp * 64);
            ldsm4(qh1, qHaddr + kp * 64 + 32);
#pragma unroll
            for (int ng = 0; ng < 4; ng++) {
                uint32_t kh[4];
                ldsm4(kh, sb + SKH(cur) + (uint32_t)(ng * 8) * RSTRIDE + kp * 64 + kfoff);
                mma16816(S[ng], qh0, kh + 0);
                mma16816(S[ng], qh1, kh + 2);
            }
        }

        // ---- mask -> -inf, f16x2 exp, p = e*invl (p words ARE the A-frags) ----
        uint32_t p0[4], p1[4];
#pragma unroll
        for (int ng = 0; ng < 4; ng++) {
            int j = 8 * ng + 2 * t4;
            float s00 = ((w0c >> j) & 1u)       ? S[ng][0] : MASKED_S;
            float s01 = ((w0c >> (j + 1)) & 1u) ? S[ng][1] : MASKED_S;
            float s10 = ((w1c >> j) & 1u)       ? S[ng][2] : MASKED_S;
            float s11 = ((w1c >> (j + 1)) & 1u) ? S[ng][3] : MASKED_S;
            p0[ng] = hmul2u(ex2h2(packh(s00, s01)), invl0h2);
            p1[ng] = hmul2u(ex2h2(packh(s10, s11)), invl1h2);
        }

        // ---- PV MMA (frags directly from p words) ----
        uint32_t ahi[2][4];
#pragma unroll
        for (int f = 0; f < 2; f++) {
            ahi[f][0] = p0[2*f];
            ahi[f][1] = p1[2*f];
            ahi[f][2] = p0[2*f+1];
            ahi[f][3] = p1[2*f+1];
        }
#pragma unroll
        for (int n = 0; n < 8; n++) {
            uint32_t bh4[4];
            ldsm4t(bh4, sb + SVH(cur) + vfoff + 16 * n);
            mma16816(O[n], ahi[0], bh4 + 0);
            mma16816(O[n], ahi[1], bh4 + 2);
        }

        // ---- attn writeback (convert p to f32 after MMAs) ----
#pragma unroll
        for (int ng = 0; ng < 4; ng++) {
            int col = t * KT + 8 * ng + 2 * t4;
            __stcs(reinterpret_cast<float2*>(&at0[col]), h2_to_f2(p0[ng]));
            __stcs(reinterpret_cast<float2*>(&at1[col]), h2_to_f2(p1[ng]));
        }

        if (t + 1 < NTILES) {
            const int nxt = cur ^ 1;
            sts_f4h(sm, SKH(nxt), tid, pk0);
            sts_f4h(sm, SKH(nxt), 256 + tid, pk1);
            sts_f4h(sm, SVH(nxt), tid, pv0);
            sts_f4h(sm, SVH(nxt), 256 + tid, pv1);
        }
    }

    float* outb = outg + (bh * SQ + (size_t)q0) * DH;
#pragma unroll
    for (int n = 0; n < 8; n++) {
        int col = 8 * n + 2 * t4;
        *reinterpret_cast<float2*>(&outb[(size_t)r0 * DH + col]) = make_float2(O[n][0], O[n][1]);
        *reinterpret_cast<float2*>(&outb[(size_t)r1 * DH + col]) = make_float2(O[n][2], O[n][3]);
    }
}

extern "C" void kernel_launch(void* const* d_in, const int* in_sizes, int n_in,
                              void* d_out, int out_size) {
    const float* q   = (const float*)d_in[0];
    const float* k   = (const float*)d_in[1];
    const float* v   = (const float*)d_in[2];
    const int*   msk = (const int*)d_in[3];
    float* out = (float*)d_out;

    cudaFuncSetAttribute(sdpa_pass0, cudaFuncAttributeMaxDynamicSharedMemorySize, SMEM_0);
    cudaFuncSetAttribute(sdpa_pass1, cudaFuncAttributeMaxDynamicSharedMemorySize, SMEM_1);

    maskpack_kernel<<<(NB_ * SQ * SQ) / (128 * 8), 256>>>(msk);
    dim3 grid(SQ / 128, NH_, NB_);
    sdpa_pass0<<<grid, 256, SMEM_0>>>(q, k);
    sdpa_pass1<<<grid, 256, SMEM_1>>>(q, k, v, out);
}

// round 16
// speedup vs baseline: 1.5070x; 1.1017x over previous
#include <cuda_runtime.h>
#include <cuda_fp16.h>
#include <stdint.h>

#define SQ 2048
#define DH 64
#define NH_ 16
#define NB_ 4
#define KT 32
#define NTILES (SQ/KT)
#define OUT_ELEMS (NB_*NH_*SQ*DH)
#define RSTRIDE 144
#define QSCALE 0.18033688011112042f   // 0.125 * log2(e); exp(s) = exp2(S)

__device__ unsigned g_maskbits[(size_t)NB_ * SQ * (SQ / 32)];   // 2 MB
__device__ float    g_linv[(size_t)NB_ * NH_ * SQ];             // 512 KB
__device__ uint2    g_kh16[(size_t)NB_ * NH_ * SQ * DH / 4];    // 16 MB fp16 (K*QSCALE)
__device__ uint2    g_vh16[(size_t)NB_ * NH_ * SQ * DH / 4];    // 16 MB fp16 V

// pass0 smem: Q hi + K hi double buffer
#define P0_QH 0
#define P0_KH(bf) (18432 + (bf)*4608)
#define SMEM_0 27648
// pass1 smem: Q hi + K hi double + V hi double
#define SQH 0
#define SKH(bf) (18432 + (bf)*4608)
#define SVH(bf) (27648 + (bf)*4608)
#define SMEM_1 36864

// ---------------- PTX helpers ----------------
__device__ __forceinline__ void ldsm4(uint32_t* r, uint32_t a) {
    asm volatile("ldmatrix.sync.aligned.m8n8.x4.shared.b16 {%0,%1,%2,%3}, [%4];"
                 : "=r"(r[0]), "=r"(r[1]), "=r"(r[2]), "=r"(r[3]) : "r"(a));
}
__device__ __forceinline__ void ldsm4t(uint32_t* r, uint32_t a) {
    asm volatile("ldmatrix.sync.aligned.m8n8.x4.trans.shared.b16 {%0,%1,%2,%3}, [%4];"
                 : "=r"(r[0]), "=r"(r[1]), "=r"(r[2]), "=r"(r[3]) : "r"(a));
}
__device__ __forceinline__ void mma16816(float* c, const uint32_t* a, const uint32_t* b) {
    asm volatile("mma.sync.aligned.m16n8k16.row.col.f32.f16.f16.f32 "
                 "{%0,%1,%2,%3}, {%4,%5,%6,%7}, {%8,%9}, {%0,%1,%2,%3};"
                 : "+f"(c[0]), "+f"(c[1]), "+f"(c[2]), "+f"(c[3])
                 : "r"(a[0]), "r"(a[1]), "r"(a[2]), "r"(a[3]), "r"(b[0]), "r"(b[1]));
}
__device__ __forceinline__ float ex2(float x) {
    float y;
    asm("ex2.approx.ftz.f32 %0, %1;" : "=f"(y) : "f"(x));
    return y;
}
__device__ __forceinline__ uint32_t packh(float x, float y) {
    __half2 h = __halves2half2(__float2half_rn(x), __float2half_rn(y));
    return *reinterpret_cast<uint32_t*>(&h);
}
__device__ __forceinline__ void sts_f4h(char* sm, int off, int lin, float4 x) {
    uint32_t a = (uint32_t)(lin >> 4) * RSTRIDE + (uint32_t)(lin & 15) * 8;
    *reinterpret_cast<uint2*>(sm + off + a) = make_uint2(packh(x.x, x.y), packh(x.z, x.w));
}
__device__ __forceinline__ void cpasync16(uint32_t dst, const void* src) {
    asm volatile("cp.async.cg.shared.global [%0], [%1], 16;" :: "r"(dst), "l"(src) : "memory");
}
#define CP_COMMIT() asm volatile("cp.async.commit_group;" ::: "memory")
#define CP_WAIT0()  asm volatile("cp.async.wait_group 0;"  ::: "memory")

// ---------------- prep: mask bit-pack + K/V fp16 conversion ----------------
__global__ void maskpack_kernel(const int* __restrict__ mask) {
    int gwarp = blockIdx.x * 8 + (threadIdx.x >> 5);
    int lane = threadIdx.x & 31;
    size_t base = (size_t)gwarp * 128;
    unsigned b0 = __ballot_sync(0xffffffffu, mask[base + lane] != 0);
    unsigned b1 = __ballot_sync(0xffffffffu, mask[base + 32 + lane] != 0);
    unsigned b2 = __ballot_sync(0xffffffffu, mask[base + 64 + lane] != 0);
    unsigned b3 = __ballot_sync(0xffffffffu, mask[base + 96 + lane] != 0);
    if (lane == 0)
        *reinterpret_cast<uint4*>(&g_maskbits[(size_t)gwarp * 4]) = make_uint4(b0, b1, b2, b3);
}

__global__ void prep_kv(const float* __restrict__ kg, const float* __restrict__ vg) {
    size_t i = (size_t)blockIdx.x * 256 + threadIdx.x;   // float4 index
    float4 kk = reinterpret_cast<const float4*>(kg)[i];
    float4 vv = reinterpret_cast<const float4*>(vg)[i];
    g_kh16[i] = make_uint2(packh(kk.x * QSCALE, kk.y * QSCALE),
                           packh(kk.z * QSCALE, kk.w * QSCALE));
    g_vh16[i] = make_uint2(packh(vv.x, vv.y), packh(vv.z, vv.w));
}

// ---------------- pass0: lsum via single-term fp16 QK (cp.async K) ----------------
__global__ __launch_bounds__(256, 4)
void sdpa_pass0(const float* __restrict__ qg)
{
    extern __shared__ char sm[];
    const uint32_t sb = (uint32_t)__cvta_generic_to_shared(sm);
    const int tid = threadIdx.x, warp = tid >> 5, lane = tid & 31;
    const int g = lane >> 2, t4 = lane & 3;
    const int qt = blockIdx.x, h = blockIdx.y, b = blockIdx.z;
    const int q0 = qt * 128;
    const size_t bh = (size_t)(b * NH_ + h);
    const float* qb = qg + (bh * SQ + (size_t)q0) * DH;
    const char* kh16 = reinterpret_cast<const char*>(g_kh16) + bh * SQ * 128;
    const int r0 = warp * 16 + g, r1 = r0 + 8;
    const int krow = tid >> 3, kchk = tid & 7;   // 32 rows x 8 chunks of 16B

    // stage Q (f32 -> f16, no scale: scale folded into K)
#pragma unroll
    for (int i = 0; i < 8; i++) {
        int lin = i * 256 + tid;
        sts_f4h(sm, P0_QH, lin, reinterpret_cast<const float4*>(qb)[lin]);
    }
    // prologue: async-load K tile 0
    cpasync16(sb + P0_KH(0) + (uint32_t)krow * RSTRIDE + kchk * 16,
              kh16 + (size_t)krow * 128 + kchk * 16);
    CP_COMMIT();

    float lsum0 = 0.0f, lsum1 = 0.0f;
    const uint32_t qHaddr = sb + P0_QH + (uint32_t)(warp * 16 + (lane & 15)) * RSTRIDE
                          + (uint32_t)(lane >> 4) * 16;
    const uint32_t kfoff = (uint32_t)(lane & 7) * RSTRIDE + (uint32_t)(lane >> 3) * 16;
    const unsigned* mw0 = &g_maskbits[((size_t)b * SQ + q0 + r0) * (SQ / 32)];
    const unsigned* mw1 = &g_maskbits[((size_t)b * SQ + q0 + r1) * (SQ / 32)];

    unsigned w0 = mw0[0], w1 = mw1[0];
    for (int t = 0; t < NTILES; t++) {
        const int cur = t & 1;
        unsigned w0c = w0, w1c = w1;
        CP_WAIT0();          // tile t data arrived (this thread's copy)
        __syncthreads();     // all copies visible; prev compute closed
        if (t + 1 < NTILES) {   // async-fill next buffer while computing
            cpasync16(sb + P0_KH(cur ^ 1) + (uint32_t)krow * RSTRIDE + kchk * 16,
                      kh16 + ((size_t)(t + 1) * KT + krow) * 128 + kchk * 16);
            CP_COMMIT();
            w0 = mw0[t + 1]; w1 = mw1[t + 1];
        }

        float S[4][4];
#pragma unroll
        for (int ng = 0; ng < 4; ng++)
#pragma unroll
            for (int j = 0; j < 4; j++) S[ng][j] = 0.0f;

#pragma unroll
        for (int kp = 0; kp < 2; kp++) {
            uint32_t qh0[4], qh1[4];
            ldsm4(qh0, qHaddr + kp * 64);
            ldsm4(qh1, qHaddr + kp * 64 + 32);
#pragma unroll
            for (int ng = 0; ng < 4; ng++) {
                uint32_t kh[4];
                ldsm4(kh, sb + P0_KH(cur) + (uint32_t)(ng * 8) * RSTRIDE + kp * 64 + kfoff);
                mma16816(S[ng], qh0, kh + 0);
                mma16816(S[ng], qh1, kh + 2);
            }
        }

#pragma unroll
        for (int ng = 0; ng < 4; ng++) {
            int j = 8 * ng + 2 * t4;
            lsum0 += (((w0c >> j) & 1u)       ? ex2(S[ng][0]) : 0.0f)
                   + (((w0c >> (j + 1)) & 1u) ? ex2(S[ng][1]) : 0.0f);
            lsum1 += (((w1c >> j) & 1u)       ? ex2(S[ng][2]) : 0.0f)
                   + (((w1c >> (j + 1)) & 1u) ? ex2(S[ng][3]) : 0.0f);
        }
    }

    lsum0 += __shfl_xor_sync(0xffffffffu, lsum0, 1);
    lsum0 += __shfl_xor_sync(0xffffffffu, lsum0, 2);
    lsum1 += __shfl_xor_sync(0xffffffffu, lsum1, 1);
    lsum1 += __shfl_xor_sync(0xffffffffu, lsum1, 2);
    if (t4 == 0) {
        g_linv[bh * SQ + q0 + r0] = 1.0f / lsum0;
        g_linv[bh * SQ + q0 + r1] = 1.0f / lsum1;
    }
}

// ---------------- pass1: QK 1-term; attn = p*invl; O += P_hi V_hi (cp.async K+V) ----------------
__global__ __launch_bounds__(256, 2)
void sdpa_pass1(const float* __restrict__ qg, float* __restrict__ outg)
{
    extern __shared__ char sm[];
    const uint32_t sb = (uint32_t)__cvta_generic_to_shared(sm);
    const int tid = threadIdx.x, warp = tid >> 5, lane = tid & 31;
    const int g = lane >> 2, t4 = lane & 3;
    const int qt = blockIdx.x, h = blockIdx.y, b = blockIdx.z;
    const int q0 = qt * 128;
    const size_t bh = (size_t)(b * NH_ + h);
    const float* qb = qg + (bh * SQ + (size_t)q0) * DH;
    const char* kh16 = reinterpret_cast<const char*>(g_kh16) + bh * SQ * 128;
    const char* vh16 = reinterpret_cast<const char*>(g_vh16) + bh * SQ * 128;
    const int r0 = warp * 16 + g, r1 = r0 + 8;
    const int krow = tid >> 3, kchk = tid & 7;

    const float invl0 = g_linv[bh * SQ + q0 + r0];
    const float invl1 = g_linv[bh * SQ + q0 + r1];

#pragma unroll
    for (int i = 0; i < 8; i++) {
        int lin = i * 256 + tid;
        sts_f4h(sm, SQH, lin, reinterpret_cast<const float4*>(qb)[lin]);
    }
    cpasync16(sb + SKH(0) + (uint32_t)krow * RSTRIDE + kchk * 16,
              kh16 + (size_t)krow * 128 + kchk * 16);
    cpasync16(sb + SVH(0) + (uint32_t)krow * RSTRIDE + kchk * 16,
              vh16 + (size_t)krow * 128 + kchk * 16);
    CP_COMMIT();

    float O[8][4];
#pragma unroll
    for (int n = 0; n < 8; n++)
#pragma unroll
        for (int j = 0; j < 4; j++) O[n][j] = 0.0f;

    const uint32_t qHaddr = sb + SQH + (uint32_t)(warp * 16 + (lane & 15)) * RSTRIDE
                          + (uint32_t)(lane >> 4) * 16;
    const uint32_t kfoff = (uint32_t)(lane & 7) * RSTRIDE + (uint32_t)(lane >> 3) * 16;
    const uint32_t vfoff = (uint32_t)(8 * (lane >> 3) + (lane & 7)) * RSTRIDE;
    const unsigned* mw0 = &g_maskbits[((size_t)b * SQ + q0 + r0) * (SQ / 32)];
    const unsigned* mw1 = &g_maskbits[((size_t)b * SQ + q0 + r1) * (SQ / 32)];
    float* attnb = outg + (size_t)OUT_ELEMS + (bh * SQ + (size_t)q0) * SQ;
    float* at0 = attnb + (size_t)r0 * SQ;
    float* at1 = attnb + (size_t)r1 * SQ;

    unsigned w0 = mw0[0], w1 = mw1[0];
    for (int t = 0; t < NTILES; t++) {
        const int cur = t & 1;
        unsigned w0c = w0, w1c = w1;
        CP_WAIT0();
        __syncthreads();
        if (t + 1 < NTILES) {
            cpasync16(sb + SKH(cur ^ 1) + (uint32_t)krow * RSTRIDE + kchk * 16,
                      kh16 + ((size_t)(t + 1) * KT + krow) * 128 + kchk * 16);
            cpasync16(sb + SVH(cur ^ 1) + (uint32_t)krow * RSTRIDE + kchk * 16,
                      vh16 + ((size_t)(t + 1) * KT + krow) * 128 + kchk * 16);
            CP_COMMIT();
            w0 = mw0[t + 1]; w1 = mw1[t + 1];
        }

        // ---- S = Q_h K_h^T (identical arithmetic to pass0) ----
        float S[4][4];
#pragma unroll
        for (int ng = 0; ng < 4; ng++)
#pragma unroll
            for (int j = 0; j < 4; j++) S[ng][j] = 0.0f;

#pragma unroll
        for (int kp = 0; kp < 2; kp++) {
            uint32_t qh0[4], qh1[4];
            ldsm4(qh0, qHaddr + kp * 64);
            ldsm4(qh1, qHaddr + kp * 64 + 32);
#pragma unroll
            for (int ng = 0; ng < 4; ng++) {
                uint32_t kh[4];
                ldsm4(kh, sb + SKH(cur) + (uint32_t)(ng * 8) * RSTRIDE + kp * 64 + kfoff);
                mma16816(S[ng], qh0, kh + 0);
                mma16816(S[ng], qh1, kh + 2);
            }
        }

        // ---- p = mask*exp2(S)*invl ----
#pragma unroll
        for (int ng = 0; ng < 4; ng++) {
            int j = 8 * ng + 2 * t4;
            S[ng][0] = ((w0c >> j) & 1u)       ? ex2(S[ng][0]) * invl0 : 0.0f;
            S[ng][1] = ((w0c >> (j + 1)) & 1u) ? ex2(S[ng][1]) * invl0 : 0.0f;
            S[ng][2] = ((w1c >> j) & 1u)       ? ex2(S[ng][2]) * invl1 : 0.0f;
            S[ng][3] = ((w1c >> (j + 1)) & 1u) ? ex2(S[ng][3]) * invl1 : 0.0f;
        }

        // ---- pack + PV MMA ----
        uint32_t ahi[2][4];
#pragma unroll
        for (int f = 0; f < 2; f++) {
            ahi[f][0] = packh(S[2*f][0],   S[2*f][1]);
            ahi[f][1] = packh(S[2*f][2],   S[2*f][3]);
            ahi[f][2] = packh(S[2*f+1][0], S[2*f+1][1]);
            ahi[f][3] = packh(S[2*f+1][2], S[2*f+1][3]);
        }
#pragma unroll
        for (int n = 0; n < 8; n++) {
            uint32_t bh4[4];
            ldsm4t(bh4, sb + SVH(cur) + vfoff + 16 * n);
            mma16816(O[n], ahi[0], bh4 + 0);
            mma16816(O[n], ahi[1], bh4 + 2);
        }

        // ---- attn writeback ----
#pragma unroll
        for (int ng = 0; ng < 4; ng++) {
            int col = t * KT + 8 * ng + 2 * t4;
            __stcs(reinterpret_cast<float2*>(&at0[col]), make_float2(S[ng][0], S[ng][1]));
            __stcs(reinterpret_cast<float2*>(&at1[col]), make_float2(S[ng][2], S[ng][3]));
        }
    }

    float* outb = outg + (bh * SQ + (size_t)q0) * DH;
#pragma unroll
    for (int n = 0; n < 8; n++) {
        int col = 8 * n + 2 * t4;
        *reinterpret_cast<float2*>(&outb[(size_t)r0 * DH + col]) = make_float2(O[n][0], O[n][1]);
        *reinterpret_cast<float2*>(&outb[(size_t)r1 * DH + col]) = make_float2(O[n][2], O[n][3]);
    }
}

extern "C" void kernel_launch(void* const* d_in, const int* in_sizes, int n_in,
                              void* d_out, int out_size) {
    const float* q   = (const float*)d_in[0];
    const float* k   = (const float*)d_in[1];
    const float* v   = (const float*)d_in[2];
    const int*   msk = (const int*)d_in[3];
    float* out = (float*)d_out;

    cudaFuncSetAttribute(sdpa_pass0, cudaFuncAttributeMaxDynamicSharedMemorySize, SMEM_0);
    cudaFuncSetAttribute(sdpa_pass1, cudaFuncAttributeMaxDynamicSharedMemorySize, SMEM_1);

    maskpack_kernel<<<(NB_ * SQ * SQ) / (128 * 8), 256>>>(msk);
    prep_kv<<<(NB_ * NH_ * SQ * DH / 4) / 256, 256>>>(k, v);
    dim3 grid(SQ / 128, NH_, NB_);
    sdpa_pass0<<<grid, 256, SMEM_0>>>(q);
    sdpa_pass1<<<grid, 256, SMEM_1>>>(q, out);
}